// round 1
// baseline (speedup 1.0000x reference)
#include <cuda_runtime.h>
#include <cuda_bf16.h>
#include <cstdint>

// ---------------------------------------------------------------------------
// GCN 3-layer forward, fp32.
//   per layer: tmp = (X @ W) * norm ; agg = scatter_add(tmp[src] -> dst)
//              x = agg*norm + b ; (layers 1,2) h = relu(x/rownorm(x) - colmean(x))
// Scratch in __device__ globals (no allocations). All launches on default
// stream, graph-capturable (kernels + cudaMemsetAsync only).
// ---------------------------------------------------------------------------

#define NMAX 50000
#define FMAX 128

__device__ float g_tmp[(size_t)NMAX * FMAX];
__device__ float g_agg[(size_t)NMAX * FMAX];
__device__ float g_x  [(size_t)NMAX * FMAX];
__device__ float g_h  [(size_t)NMAX * FMAX];
__device__ float g_colsum[FMAX];

// ---------------------------------------------------------------------------
// GEMM: C[m][n] = (sum_k A[m][k]*B[k][n]) * norm[m]
// A: [M,K] row-major, B: [K,N] row-major. BM=64 tile, full N per block.
// ---------------------------------------------------------------------------
template <int K, int N>
__global__ __launch_bounds__(256) void gemm_norm_kernel(
    const float* __restrict__ A, const float* __restrict__ B,
    const float* __restrict__ norm, float* __restrict__ C, int M)
{
    constexpr int BM = 64;
    constexpr int BK = 32;
    constexpr int TX = N / 8;        // threads along n (each covers 8 cols)
    constexpr int TY = 256 / TX;     // threads along m
    constexpr int TM = BM / TY;      // rows per thread

    __shared__ float As[BK][BM + 1]; // +1 pad: avoid store bank conflicts
    __shared__ float Bs[BK][N];

    const int tid = threadIdx.x;
    const int tx = tid % TX;
    const int ty = tid / TX;
    const int row0 = blockIdx.x * BM;

    float acc[TM][8];
#pragma unroll
    for (int i = 0; i < TM; i++)
#pragma unroll
        for (int j = 0; j < 8; j++) acc[i][j] = 0.0f;

    for (int k0 = 0; k0 < K; k0 += BK) {
        // Load A tile (BM x BK) as float4, store transposed into As[k][m].
#pragma unroll
        for (int i = tid; i < BM * (BK / 4); i += 256) {
            int r  = i / (BK / 4);
            int cc = i % (BK / 4);
            float4 v = make_float4(0.f, 0.f, 0.f, 0.f);
            int gr = row0 + r;
            if (gr < M)
                v = *(const float4*)(A + (size_t)gr * K + k0 + cc * 4);
            As[cc * 4 + 0][r] = v.x;
            As[cc * 4 + 1][r] = v.y;
            As[cc * 4 + 2][r] = v.z;
            As[cc * 4 + 3][r] = v.w;
        }
        // Load B tile (BK x N), direct copy.
#pragma unroll
        for (int i = tid; i < BK * (N / 4); i += 256) {
            int r  = i / (N / 4);
            int cc = i % (N / 4);
            *(float4*)&Bs[r][cc * 4] =
                *(const float4*)(B + (size_t)(k0 + r) * N + cc * 4);
        }
        __syncthreads();

#pragma unroll
        for (int kk = 0; kk < BK; kk++) {
            float a[TM], b[8];
#pragma unroll
            for (int i = 0; i < TM; i++) a[i] = As[kk][ty * TM + i];
#pragma unroll
            for (int j = 0; j < 8; j++) b[j] = Bs[kk][tx * 8 + j];
#pragma unroll
            for (int i = 0; i < TM; i++)
#pragma unroll
                for (int j = 0; j < 8; j++) acc[i][j] += a[i] * b[j];
        }
        __syncthreads();
    }

#pragma unroll
    for (int i = 0; i < TM; i++) {
        int gr = row0 + ty * TM + i;
        if (gr >= M) continue;
        float nm = norm[gr];
        float4 o0 = make_float4(acc[i][0] * nm, acc[i][1] * nm,
                                acc[i][2] * nm, acc[i][3] * nm);
        float4 o1 = make_float4(acc[i][4] * nm, acc[i][5] * nm,
                                acc[i][6] * nm, acc[i][7] * nm);
        float* cp = C + (size_t)gr * N + tx * 8;
        *(float4*)(cp + 0) = o0;
        *(float4*)(cp + 4) = o1;
    }
}

// ---------------------------------------------------------------------------
// Edge scatter: agg[dst[e]] += tmp[src[e]]   (vectorized red.global.add.v4.f32)
// N4 = feature_dim / 4. thread -> (edge, float4-chunk).
// ---------------------------------------------------------------------------
__device__ __forceinline__ void red_add_v4(float* p, float4 v) {
    asm volatile("red.global.add.v4.f32 [%0], {%1, %2, %3, %4};"
                 :: "l"(p), "f"(v.x), "f"(v.y), "f"(v.z), "f"(v.w)
                 : "memory");
}

template <int N4>
__global__ __launch_bounds__(256) void scatter_kernel(
    const float4* __restrict__ tmp, const int* __restrict__ src,
    const int* __restrict__ dst, float* __restrict__ agg, int n_edges)
{
    int tid = blockIdx.x * blockDim.x + threadIdx.x;
    int e = tid / N4;
    int c = tid % N4;
    if (e >= n_edges) return;
    int s = __ldg(src + e);
    int d = __ldg(dst + e);
    float4 v = tmp[(size_t)s * N4 + c];
    red_add_v4(agg + ((size_t)d * N4 + c) * 4, v);
}

// ---------------------------------------------------------------------------
// post_a: x = agg*norm + b, accumulate column sums into colsum (for pairnorm)
// ---------------------------------------------------------------------------
template <int N>
__global__ __launch_bounds__(256) void post_a_kernel(
    const float* __restrict__ agg, const float* __restrict__ norm,
    const float* __restrict__ bias, float* __restrict__ x,
    float* __restrict__ colsum, int M)
{
    constexpr int N4 = N / 4;
    constexpr int RPB = 256 / N4;
    __shared__ float scol[N];

    const int c = threadIdx.x % N4;
    const int rl = threadIdx.x / N4;
    float4 bb = ((const float4*)bias)[c];
    float4 lsum = make_float4(0.f, 0.f, 0.f, 0.f);

    for (int r = blockIdx.x * RPB + rl; r < M; r += gridDim.x * RPB) {
        float nm = norm[r];
        float4 v = ((const float4*)agg)[(size_t)r * N4 + c];
        v.x = v.x * nm + bb.x;
        v.y = v.y * nm + bb.y;
        v.z = v.z * nm + bb.z;
        v.w = v.w * nm + bb.w;
        ((float4*)x)[(size_t)r * N4 + c] = v;
        lsum.x += v.x; lsum.y += v.y; lsum.z += v.z; lsum.w += v.w;
    }

    if (threadIdx.x < N) scol[threadIdx.x] = 0.0f;
    __syncthreads();
    atomicAdd(&scol[c * 4 + 0], lsum.x);
    atomicAdd(&scol[c * 4 + 1], lsum.y);
    atomicAdd(&scol[c * 4 + 2], lsum.z);
    atomicAdd(&scol[c * 4 + 3], lsum.w);
    __syncthreads();
    if (threadIdx.x < N) atomicAdd(&colsum[threadIdx.x], scol[threadIdx.x]);
}

// ---------------------------------------------------------------------------
// post_b: h = relu(x / sqrt(1e-6 + sum(x^2,row)) - colsum/M). One warp per row.
// ---------------------------------------------------------------------------
template <int N>
__global__ __launch_bounds__(256) void post_b_kernel(
    const float* __restrict__ x, const float* __restrict__ colsum,
    float* __restrict__ h, int M)
{
    constexpr int PER = N / 32;
    int warp = (blockIdx.x * blockDim.x + threadIdx.x) >> 5;
    int lane = threadIdx.x & 31;
    if (warp >= M) return;

    float v[PER];
    float ss = 0.0f;
#pragma unroll
    for (int p = 0; p < PER; p++) {
        v[p] = x[(size_t)warp * N + p * 32 + lane];
        ss += v[p] * v[p];
    }
#pragma unroll
    for (int o = 16; o > 0; o >>= 1)
        ss += __shfl_xor_sync(0xffffffffu, ss, o);

    float rinv = rsqrtf(1e-6f + ss);
    float invM = 1.0f / (float)M;
#pragma unroll
    for (int p = 0; p < PER; p++) {
        float cm = colsum[p * 32 + lane] * invM;
        float o = v[p] * rinv - cm;
        h[(size_t)warp * N + p * 32 + lane] = fmaxf(o, 0.0f);
    }
}

// ---------------------------------------------------------------------------
// Final layer epilogue (no pairnorm): out = agg*norm + b   (N = 64)
// ---------------------------------------------------------------------------
__global__ __launch_bounds__(256) void final_kernel(
    const float* __restrict__ agg, const float* __restrict__ norm,
    const float* __restrict__ bias, float* __restrict__ out, int M)
{
    constexpr int N4 = 64 / 4;
    int tid = blockIdx.x * blockDim.x + threadIdx.x;
    if (tid >= M * N4) return;
    int r = tid / N4;
    int c = tid % N4;
    float nm = norm[r];
    float4 v = ((const float4*)agg)[(size_t)r * N4 + c];
    float4 bb = ((const float4*)bias)[c];
    v.x = v.x * nm + bb.x;
    v.y = v.y * nm + bb.y;
    v.z = v.z * nm + bb.z;
    v.w = v.w * nm + bb.w;
    ((float4*)out)[(size_t)r * N4 + c] = v;
}

// ---------------------------------------------------------------------------
// Launch
// ---------------------------------------------------------------------------
extern "C" void kernel_launch(void* const* d_in, const int* in_sizes, int n_in,
                              void* d_out, int out_size)
{
    const float* in_feat = (const float*)d_in[0];
    const int*   src     = (const int*)  d_in[1];
    const int*   dst     = (const int*)  d_in[2];
    const float* norm    = (const float*)d_in[3];
    const float* W1      = (const float*)d_in[4];
    const float* b1      = (const float*)d_in[5];
    const float* W2      = (const float*)d_in[6];
    const float* b2      = (const float*)d_in[7];
    const float* W3      = (const float*)d_in[8];
    const float* b3      = (const float*)d_in[9];
    float* out = (float*)d_out;

    const int M = in_sizes[3];   // 50000 nodes (norm length)
    const int E = in_sizes[1];   // 800000 edges

    float *tmp, *agg, *x, *h, *colsum;
    cudaGetSymbolAddress((void**)&tmp,    g_tmp);
    cudaGetSymbolAddress((void**)&agg,    g_agg);
    cudaGetSymbolAddress((void**)&x,      g_x);
    cudaGetSymbolAddress((void**)&h,      g_h);
    cudaGetSymbolAddress((void**)&colsum, g_colsum);

    const int gemm_blocks = (M + 63) / 64;

    // ---------------- Layer 1: 256 -> 128 ----------------
    gemm_norm_kernel<256, 128><<<gemm_blocks, 256>>>(in_feat, W1, norm, tmp, M);
    cudaMemsetAsync(agg, 0, (size_t)M * 128 * sizeof(float));
    scatter_kernel<32><<<(E * 32 + 255) / 256, 256>>>(
        (const float4*)tmp, src, dst, agg, E);
    cudaMemsetAsync(colsum, 0, 128 * sizeof(float));
    post_a_kernel<128><<<1024, 256>>>(agg, norm, b1, x, colsum, M);
    post_b_kernel<128><<<(M + 7) / 8, 256>>>(x, colsum, h, M);

    // ---------------- Layer 2: 128 -> 128 ----------------
    gemm_norm_kernel<128, 128><<<gemm_blocks, 256>>>(h, W2, norm, tmp, M);
    cudaMemsetAsync(agg, 0, (size_t)M * 128 * sizeof(float));
    scatter_kernel<32><<<(E * 32 + 255) / 256, 256>>>(
        (const float4*)tmp, src, dst, agg, E);
    cudaMemsetAsync(colsum, 0, 128 * sizeof(float));
    post_a_kernel<128><<<1024, 256>>>(agg, norm, b2, x, colsum, M);
    post_b_kernel<128><<<(M + 7) / 8, 256>>>(x, colsum, h, M);

    // ---------------- Layer 3: 128 -> 64 ----------------
    gemm_norm_kernel<128, 64><<<gemm_blocks, 256>>>(h, W3, norm, tmp, M);
    cudaMemsetAsync(agg, 0, (size_t)M * 64 * sizeof(float));
    scatter_kernel<16><<<(E * 16 + 255) / 256, 256>>>(
        (const float4*)tmp, src, dst, agg, E);
    final_kernel<<<(M * 16 + 255) / 256, 256>>>(agg, norm, b3, out, M);
}

// round 2
// speedup vs baseline: 1.1895x; 1.1895x over previous
#include <cuda_runtime.h>
#include <cuda_bf16.h>
#include <cstdint>

// ---------------------------------------------------------------------------
// GCN 3-layer forward, fp32.
// Round 2: replace atomic scatter with CSR-gather aggregation.
//   once:   build dst-CSR (deg histogram -> scan -> slot fill)
//   layer:  tmp = (X @ W) * norm                       [gemm_norm]
//           x   = (sum_{e: dst=r} tmp[src_e])*norm + b [gather, fuses post_a]
//           h   = relu(x/rownorm - colmean)            [post_b]  (layers 1,2)
// ---------------------------------------------------------------------------

#define NMAX 50000
#define EMAX 800000
#define FMAX 128

__device__ float g_tmp[(size_t)NMAX * FMAX];
__device__ float g_x  [(size_t)NMAX * FMAX];
__device__ float g_h  [(size_t)NMAX * FMAX];
__device__ float g_colsum[FMAX];
__device__ int   g_deg [NMAX];
__device__ int   g_off [NMAX + 1];
__device__ int   g_cur [NMAX];
__device__ int   g_csrc[EMAX];

// ---------------------------------------------------------------------------
// GEMM: C[m][n] = (sum_k A[m][k]*B[k][n]) * norm[m]
// ---------------------------------------------------------------------------
template <int K, int N>
__global__ __launch_bounds__(256) void gemm_norm_kernel(
    const float* __restrict__ A, const float* __restrict__ B,
    const float* __restrict__ norm, float* __restrict__ C, int M)
{
    constexpr int BM = 64;
    constexpr int BK = 32;
    constexpr int TX = N / 8;
    constexpr int TY = 256 / TX;
    constexpr int TM = BM / TY;

    __shared__ float As[BK][BM + 1];
    __shared__ float Bs[BK][N];

    const int tid = threadIdx.x;
    const int tx = tid % TX;
    const int ty = tid / TX;
    const int row0 = blockIdx.x * BM;

    float acc[TM][8];
#pragma unroll
    for (int i = 0; i < TM; i++)
#pragma unroll
        for (int j = 0; j < 8; j++) acc[i][j] = 0.0f;

    for (int k0 = 0; k0 < K; k0 += BK) {
#pragma unroll
        for (int i = tid; i < BM * (BK / 4); i += 256) {
            int r  = i / (BK / 4);
            int cc = i % (BK / 4);
            float4 v = make_float4(0.f, 0.f, 0.f, 0.f);
            int gr = row0 + r;
            if (gr < M)
                v = *(const float4*)(A + (size_t)gr * K + k0 + cc * 4);
            As[cc * 4 + 0][r] = v.x;
            As[cc * 4 + 1][r] = v.y;
            As[cc * 4 + 2][r] = v.z;
            As[cc * 4 + 3][r] = v.w;
        }
#pragma unroll
        for (int i = tid; i < BK * (N / 4); i += 256) {
            int r  = i / (N / 4);
            int cc = i % (N / 4);
            *(float4*)&Bs[r][cc * 4] =
                *(const float4*)(B + (size_t)(k0 + r) * N + cc * 4);
        }
        __syncthreads();

#pragma unroll
        for (int kk = 0; kk < BK; kk++) {
            float a[TM], b[8];
#pragma unroll
            for (int i = 0; i < TM; i++) a[i] = As[kk][ty * TM + i];
#pragma unroll
            for (int j = 0; j < 8; j++) b[j] = Bs[kk][tx * 8 + j];
#pragma unroll
            for (int i = 0; i < TM; i++)
#pragma unroll
                for (int j = 0; j < 8; j++) acc[i][j] += a[i] * b[j];
        }
        __syncthreads();
    }

#pragma unroll
    for (int i = 0; i < TM; i++) {
        int gr = row0 + ty * TM + i;
        if (gr >= M) continue;
        float nm = norm[gr];
        float4 o0 = make_float4(acc[i][0] * nm, acc[i][1] * nm,
                                acc[i][2] * nm, acc[i][3] * nm);
        float4 o1 = make_float4(acc[i][4] * nm, acc[i][5] * nm,
                                acc[i][6] * nm, acc[i][7] * nm);
        float* cp = C + (size_t)gr * N + tx * 8;
        *(float4*)(cp + 0) = o0;
        *(float4*)(cp + 4) = o1;
    }
}

// ---------------------------------------------------------------------------
// CSR build
// ---------------------------------------------------------------------------
__global__ __launch_bounds__(256) void hist_kernel(
    const int* __restrict__ dst, int* __restrict__ deg, int E)
{
    int e = blockIdx.x * blockDim.x + threadIdx.x;
    if (e < E) atomicAdd(&deg[dst[e]], 1);
}

__global__ __launch_bounds__(1024) void scan_kernel(
    const int* __restrict__ deg, int* __restrict__ off,
    int* __restrict__ cur, int N)
{
    __shared__ int part[1024];
    const int t = threadIdx.x;
    const int chunk = (N + 1023) >> 10;
    const int start = t * chunk;
    const int end = min(start + chunk, N);

    int s = 0;
    for (int i = start; i < end; i++) s += deg[i];
    part[t] = s;
    __syncthreads();
    // Hillis-Steele inclusive scan of partials
    for (int o = 1; o < 1024; o <<= 1) {
        int v = (t >= o) ? part[t - o] : 0;
        __syncthreads();
        part[t] += v;
        __syncthreads();
    }
    int base = (t == 0) ? 0 : part[t - 1];
    for (int i = start; i < end; i++) {
        off[i] = base;
        cur[i] = base;
        base += deg[i];
    }
    if (t == 1023) off[N] = part[1023];
}

__global__ __launch_bounds__(256) void fill_kernel(
    const int* __restrict__ src, const int* __restrict__ dst,
    int* __restrict__ cur, int* __restrict__ csrc, int E)
{
    int e = blockIdx.x * blockDim.x + threadIdx.x;
    if (e >= E) return;
    int d = dst[e];
    int p = atomicAdd(&cur[d], 1);
    csrc[p] = src[e];
}

// ---------------------------------------------------------------------------
// Gather-aggregate + epilogue: x[r] = (sum_{e in row r} tmp[csrc[e]])*norm[r]+b
// N4 lanes per row (N4 = feat/4). Fuses colsum accumulation for pairnorm.
// ---------------------------------------------------------------------------
template <int N4, bool COLSUM>
__global__ __launch_bounds__(256) void gather_kernel(
    const float4* __restrict__ tmp, const int* __restrict__ off,
    const int* __restrict__ csrc, const float* __restrict__ norm,
    const float* __restrict__ bias, float4* __restrict__ xout,
    float* __restrict__ colsum, int M)
{
    constexpr int RPB = 256 / N4;
    const int lane = threadIdx.x % N4;
    const int rl = threadIdx.x / N4;

    float4 bb = ((const float4*)bias)[lane];
    float4 lsum = make_float4(0.f, 0.f, 0.f, 0.f);

    for (int r = blockIdx.x * RPB + rl; r < M; r += gridDim.x * RPB) {
        int s0 = __ldg(off + r);
        int s1 = __ldg(off + r + 1);
        float4 acc = make_float4(0.f, 0.f, 0.f, 0.f);
        int i = s0;
        for (; i + 1 < s1; i += 2) {
            int sa = __ldg(csrc + i);
            int sb = __ldg(csrc + i + 1);
            float4 va = tmp[(size_t)sa * N4 + lane];
            float4 vb = tmp[(size_t)sb * N4 + lane];
            acc.x += va.x + vb.x;
            acc.y += va.y + vb.y;
            acc.z += va.z + vb.z;
            acc.w += va.w + vb.w;
        }
        if (i < s1) {
            int sa = __ldg(csrc + i);
            float4 va = tmp[(size_t)sa * N4 + lane];
            acc.x += va.x; acc.y += va.y; acc.z += va.z; acc.w += va.w;
        }
        float nm = norm[r];
        float4 v;
        v.x = acc.x * nm + bb.x;
        v.y = acc.y * nm + bb.y;
        v.z = acc.z * nm + bb.z;
        v.w = acc.w * nm + bb.w;
        xout[(size_t)r * N4 + lane] = v;
        if (COLSUM) {
            lsum.x += v.x; lsum.y += v.y; lsum.z += v.z; lsum.w += v.w;
        }
    }

    if (COLSUM) {
        __shared__ float scol[N4 * 4];
        if (threadIdx.x < N4 * 4) scol[threadIdx.x] = 0.0f;
        __syncthreads();
        atomicAdd(&scol[lane * 4 + 0], lsum.x);
        atomicAdd(&scol[lane * 4 + 1], lsum.y);
        atomicAdd(&scol[lane * 4 + 2], lsum.z);
        atomicAdd(&scol[lane * 4 + 3], lsum.w);
        __syncthreads();
        if (threadIdx.x < N4 * 4)
            atomicAdd(&colsum[threadIdx.x], scol[threadIdx.x]);
    }
}

// ---------------------------------------------------------------------------
// post_b: h = relu(x / sqrt(1e-6 + rowsumsq) - colsum/M). One warp per row.
// ---------------------------------------------------------------------------
template <int N>
__global__ __launch_bounds__(256) void post_b_kernel(
    const float* __restrict__ x, const float* __restrict__ colsum,
    float* __restrict__ h, int M)
{
    constexpr int PER = N / 32;
    int warp = (blockIdx.x * blockDim.x + threadIdx.x) >> 5;
    int lane = threadIdx.x & 31;
    if (warp >= M) return;

    float v[PER];
    float ss = 0.0f;
#pragma unroll
    for (int p = 0; p < PER; p++) {
        v[p] = x[(size_t)warp * N + p * 32 + lane];
        ss += v[p] * v[p];
    }
#pragma unroll
    for (int o = 16; o > 0; o >>= 1)
        ss += __shfl_xor_sync(0xffffffffu, ss, o);

    float rinv = rsqrtf(1e-6f + ss);
    float invM = 1.0f / (float)M;
#pragma unroll
    for (int p = 0; p < PER; p++) {
        float cm = colsum[p * 32 + lane] * invM;
        float o = v[p] * rinv - cm;
        h[(size_t)warp * N + p * 32 + lane] = fmaxf(o, 0.0f);
    }
}

// ---------------------------------------------------------------------------
// Launch
// ---------------------------------------------------------------------------
extern "C" void kernel_launch(void* const* d_in, const int* in_sizes, int n_in,
                              void* d_out, int out_size)
{
    const float* in_feat = (const float*)d_in[0];
    const int*   src     = (const int*)  d_in[1];
    const int*   dst     = (const int*)  d_in[2];
    const float* norm    = (const float*)d_in[3];
    const float* W1      = (const float*)d_in[4];
    const float* b1      = (const float*)d_in[5];
    const float* W2      = (const float*)d_in[6];
    const float* b2      = (const float*)d_in[7];
    const float* W3      = (const float*)d_in[8];
    const float* b3      = (const float*)d_in[9];
    float* out = (float*)d_out;

    const int M = in_sizes[3];   // 50000 nodes
    const int E = in_sizes[1];   // 800000 edges

    float *tmp, *x, *h, *colsum;
    int *deg, *off, *cur, *csrc;
    cudaGetSymbolAddress((void**)&tmp,    g_tmp);
    cudaGetSymbolAddress((void**)&x,      g_x);
    cudaGetSymbolAddress((void**)&h,      g_h);
    cudaGetSymbolAddress((void**)&colsum, g_colsum);
    cudaGetSymbolAddress((void**)&deg,    g_deg);
    cudaGetSymbolAddress((void**)&off,    g_off);
    cudaGetSymbolAddress((void**)&cur,    g_cur);
    cudaGetSymbolAddress((void**)&csrc,   g_csrc);

    const int gemm_blocks = (M + 63) / 64;
    const int GATHER_BLOCKS = 2048;

    // ---------------- CSR build (graph is layer-invariant) ----------------
    cudaMemsetAsync(deg, 0, (size_t)M * sizeof(int));
    hist_kernel<<<(E + 255) / 256, 256>>>(dst, deg, E);
    scan_kernel<<<1, 1024>>>(deg, off, cur, M);
    fill_kernel<<<(E + 255) / 256, 256>>>(src, dst, cur, csrc, E);

    // ---------------- Layer 1: 256 -> 128 ----------------
    gemm_norm_kernel<256, 128><<<gemm_blocks, 256>>>(in_feat, W1, norm, tmp, M);
    cudaMemsetAsync(colsum, 0, 128 * sizeof(float));
    gather_kernel<32, true><<<GATHER_BLOCKS, 256>>>(
        (const float4*)tmp, off, csrc, norm, b1, (float4*)x, colsum, M);
    post_b_kernel<128><<<(M + 7) / 8, 256>>>(x, colsum, h, M);

    // ---------------- Layer 2: 128 -> 128 ----------------
    gemm_norm_kernel<128, 128><<<gemm_blocks, 256>>>(h, W2, norm, tmp, M);
    cudaMemsetAsync(colsum, 0, 128 * sizeof(float));
    gather_kernel<32, true><<<GATHER_BLOCKS, 256>>>(
        (const float4*)tmp, off, csrc, norm, b2, (float4*)x, colsum, M);
    post_b_kernel<128><<<(M + 7) / 8, 256>>>(x, colsum, h, M);

    // ---------------- Layer 3: 128 -> 64 ----------------
    gemm_norm_kernel<128, 64><<<gemm_blocks, 256>>>(h, W3, norm, tmp, M);
    gather_kernel<16, false><<<GATHER_BLOCKS, 256>>>(
        (const float4*)tmp, off, csrc, norm, b3, (float4*)out, nullptr, M);
}

// round 3
// speedup vs baseline: 1.6801x; 1.4125x over previous
#include <cuda_runtime.h>
#include <cuda_bf16.h>
#include <cstdint>

// ---------------------------------------------------------------------------
// GCN 3-layer forward.
// Round 3: GEMMs on tensor cores via 2-term bf16 split (hi+lo), 3 MMAs:
//   A@B ~= Ah@Bh + Ah@Bl + Al@Bh   (error ~2^-18 per product, fp32 accum)
// Aggregation stays CSR-gather (round 2).
// ---------------------------------------------------------------------------

#define NMAX 50000
#define EMAX 800000
#define FMAX 128

__device__ float g_tmp[(size_t)NMAX * FMAX];
__device__ float g_x  [(size_t)NMAX * FMAX];
__device__ float g_h  [(size_t)NMAX * FMAX];
__device__ float g_colsum[FMAX];
__device__ int   g_deg [NMAX];
__device__ int   g_off [NMAX + 1];
__device__ int   g_cur [NMAX];
__device__ int   g_csrc[EMAX];
// W transposed + split scratch: [N][K] bf16, max 128*256
__device__ uint32_t g_wth[128 * 256 / 2];
__device__ uint32_t g_wtl[128 * 256 / 2];

// ---------------------------------------------------------------------------
// W convert: Wt_hi/Wt_lo[n][k] = split(W[k][n])
// ---------------------------------------------------------------------------
__global__ __launch_bounds__(256) void wconv_kernel(
    const float* __restrict__ W, __nv_bfloat16* __restrict__ wth,
    __nv_bfloat16* __restrict__ wtl, int K, int N)
{
    int idx = blockIdx.x * blockDim.x + threadIdx.x;
    if (idx >= K * N) return;
    int n = idx / K, k = idx % K;
    float x = W[(size_t)k * N + n];
    __nv_bfloat16 h = __float2bfloat16(x);
    __nv_bfloat16 l = __float2bfloat16(x - __bfloat162float(h));
    wth[idx] = h;
    wtl[idx] = l;
}

// ---------------------------------------------------------------------------
// Tensor-core GEMM: C[m][n] = (sum_k A[m][k]*B[k][n]) * norm[m]
// A fp32 [M][K] (split on load), Wt hi/lo bf16 [N][K].
// ---------------------------------------------------------------------------
__device__ __forceinline__ void mma16816(float* c, const uint32_t* a,
                                         uint32_t b0, uint32_t b1) {
    asm volatile(
        "mma.sync.aligned.m16n8k16.row.col.f32.bf16.bf16.f32 "
        "{%0,%1,%2,%3}, {%4,%5,%6,%7}, {%8,%9}, {%0,%1,%2,%3};\n"
        : "+f"(c[0]), "+f"(c[1]), "+f"(c[2]), "+f"(c[3])
        : "r"(a[0]), "r"(a[1]), "r"(a[2]), "r"(a[3]), "r"(b0), "r"(b1));
}

__device__ __forceinline__ uint32_t pack_bf2(__nv_bfloat16 a, __nv_bfloat16 b) {
    __nv_bfloat162 p = __halves2bfloat162(a, b);
    return *reinterpret_cast<uint32_t*>(&p);
}

template <int K, int N>
__global__ __launch_bounds__(256) void gemm_tc_kernel(
    const float* __restrict__ A, const uint32_t* __restrict__ wth,
    const uint32_t* __restrict__ wtl, const float* __restrict__ norm,
    float* __restrict__ C, int M)
{
    constexpr int BM = 128;
    constexpr int BK = 32;
    constexpr int S = 20;                 // smem row stride in 32-bit words
    constexpr int WARPS_N = (N == 128) ? 2 : 1;
    constexpr int WARPS_M = 8 / WARPS_N;
    constexpr int WM = BM / WARPS_M;      // 32 or 16
    constexpr int WN = N / WARPS_N;       // 64
    constexpr int MT = WM / 16;           // 2 or 1
    constexpr int NT = WN / 8;            // 8

    __shared__ uint32_t Ah[BM * S], Al[BM * S];
    __shared__ uint32_t Bh[N * S],  Bl[N * S];

    const int tid = threadIdx.x;
    const int warp = tid >> 5;
    const int lane = tid & 31;
    const int g = lane >> 2;     // group id (row within fragment)
    const int t = lane & 3;      // thread id in group
    const int wm = warp % WARPS_M;
    const int wn = warp / WARPS_M;
    const int row0 = blockIdx.x * BM;

    float acc[MT][NT][4];
#pragma unroll
    for (int i = 0; i < MT; i++)
#pragma unroll
        for (int j = 0; j < NT; j++)
#pragma unroll
            for (int q = 0; q < 4; q++) acc[i][j][q] = 0.0f;

    for (int k0 = 0; k0 < K; k0 += BK) {
        // ---- A tile: BM x BK fp32 -> hi/lo bf16 in smem [m][k] ----
#pragma unroll
        for (int p = 0; p < BM * 8 / 256; p++) {
            int idx = tid + p * 256;
            int m = idx >> 3;           // row
            int c = idx & 7;            // float4 chunk within BK
            int gr = row0 + m;
            float4 v = make_float4(0.f, 0.f, 0.f, 0.f);
            if (gr < M)
                v = *(const float4*)(A + (size_t)gr * K + k0 + c * 4);
            __nv_bfloat16 h0 = __float2bfloat16(v.x);
            __nv_bfloat16 h1 = __float2bfloat16(v.y);
            __nv_bfloat16 h2 = __float2bfloat16(v.z);
            __nv_bfloat16 h3 = __float2bfloat16(v.w);
            __nv_bfloat16 l0 = __float2bfloat16(v.x - __bfloat162float(h0));
            __nv_bfloat16 l1 = __float2bfloat16(v.y - __bfloat162float(h1));
            __nv_bfloat16 l2 = __float2bfloat16(v.z - __bfloat162float(h2));
            __nv_bfloat16 l3 = __float2bfloat16(v.w - __bfloat162float(h3));
            int w = m * S + c * 2;
            Ah[w]     = pack_bf2(h0, h1);
            Ah[w + 1] = pack_bf2(h2, h3);
            Al[w]     = pack_bf2(l0, l1);
            Al[w + 1] = pack_bf2(l2, l3);
        }
        // ---- B tile: N x BK bf16 (already [n][k] in global) ----
#pragma unroll
        for (int p = 0; p < N * 8 / 256; p++) {
            int idx = tid + p * 256;
            int n = idx >> 3;
            int c = idx & 7;            // uint2 chunk (4 bf16)
            const uint2* ph = (const uint2*)(wth + ((size_t)n * K + k0) / 2) + c;
            const uint2* pl = (const uint2*)(wtl + ((size_t)n * K + k0) / 2) + c;
            uint2 vh = *ph, vl = *pl;
            int w = n * S + c * 2;
            *(uint2*)&Bh[w] = vh;
            *(uint2*)&Bl[w] = vl;
        }
        __syncthreads();

#pragma unroll
        for (int s = 0; s < 2; s++) {   // two k16 steps per BK=32
            uint32_t ah[MT][4], al[MT][4];
#pragma unroll
            for (int mt = 0; mt < MT; mt++) {
                int r0 = (wm * WM + mt * 16 + g) * S + s * 8 + t;
                int r1 = r0 + 8 * S;
                ah[mt][0] = Ah[r0];     ah[mt][1] = Ah[r1];
                ah[mt][2] = Ah[r0 + 4]; ah[mt][3] = Ah[r1 + 4];
                al[mt][0] = Al[r0];     al[mt][1] = Al[r1];
                al[mt][2] = Al[r0 + 4]; al[mt][3] = Al[r1 + 4];
            }
#pragma unroll
            for (int nt = 0; nt < NT; nt++) {
                int nb = (wn * WN + nt * 8 + g) * S + s * 8 + t;
                uint32_t bh0 = Bh[nb], bh1 = Bh[nb + 4];
                uint32_t bl0 = Bl[nb], bl1 = Bl[nb + 4];
#pragma unroll
                for (int mt = 0; mt < MT; mt++) {
                    mma16816(acc[mt][nt], ah[mt], bh0, bh1);
                    mma16816(acc[mt][nt], ah[mt], bl0, bl1);
                    mma16816(acc[mt][nt], al[mt], bh0, bh1);
                }
            }
        }
        __syncthreads();
    }

    // ---- epilogue: scale by norm[row], write float2 per (frag row, ntile) ----
#pragma unroll
    for (int mt = 0; mt < MT; mt++) {
        int r0 = row0 + wm * WM + mt * 16 + g;
        int r1 = r0 + 8;
        float nm0 = (r0 < M) ? norm[r0] : 0.0f;
        float nm1 = (r1 < M) ? norm[r1] : 0.0f;
#pragma unroll
        for (int nt = 0; nt < NT; nt++) {
            int cc = wn * WN + nt * 8 + 2 * t;
            if (r0 < M) {
                float2 o = make_float2(acc[mt][nt][0] * nm0,
                                       acc[mt][nt][1] * nm0);
                *(float2*)(C + (size_t)r0 * N + cc) = o;
            }
            if (r1 < M) {
                float2 o = make_float2(acc[mt][nt][2] * nm1,
                                       acc[mt][nt][3] * nm1);
                *(float2*)(C + (size_t)r1 * N + cc) = o;
            }
        }
    }
}

// ---------------------------------------------------------------------------
// CSR build
// ---------------------------------------------------------------------------
__global__ __launch_bounds__(256) void hist_kernel(
    const int* __restrict__ dst, int* __restrict__ deg, int E)
{
    int e = blockIdx.x * blockDim.x + threadIdx.x;
    if (e < E) atomicAdd(&deg[dst[e]], 1);
}

__global__ __launch_bounds__(1024) void scan_kernel(
    const int* __restrict__ deg, int* __restrict__ off,
    int* __restrict__ cur, int N)
{
    __shared__ int part[1024];
    const int t = threadIdx.x;
    const int chunk = (N + 1023) >> 10;
    const int start = t * chunk;
    const int end = min(start + chunk, N);

    int s = 0;
    for (int i = start; i < end; i++) s += deg[i];
    part[t] = s;
    __syncthreads();
    for (int o = 1; o < 1024; o <<= 1) {
        int v = (t >= o) ? part[t - o] : 0;
        __syncthreads();
        part[t] += v;
        __syncthreads();
    }
    int base = (t == 0) ? 0 : part[t - 1];
    for (int i = start; i < end; i++) {
        off[i] = base;
        cur[i] = base;
        base += deg[i];
    }
    if (t == 1023) off[N] = part[1023];
}

__global__ __launch_bounds__(256) void fill_kernel(
    const int* __restrict__ src, const int* __restrict__ dst,
    int* __restrict__ cur, int* __restrict__ csrc, int E)
{
    int e = blockIdx.x * blockDim.x + threadIdx.x;
    if (e >= E) return;
    int d = dst[e];
    int p = atomicAdd(&cur[d], 1);
    csrc[p] = src[e];
}

// ---------------------------------------------------------------------------
// Gather-aggregate + epilogue
// ---------------------------------------------------------------------------
template <int N4, bool COLSUM>
__global__ __launch_bounds__(256) void gather_kernel(
    const float4* __restrict__ tmp, const int* __restrict__ off,
    const int* __restrict__ csrc, const float* __restrict__ norm,
    const float* __restrict__ bias, float4* __restrict__ xout,
    float* __restrict__ colsum, int M)
{
    constexpr int RPB = 256 / N4;
    const int lane = threadIdx.x % N4;
    const int rl = threadIdx.x / N4;

    float4 bb = ((const float4*)bias)[lane];
    float4 lsum = make_float4(0.f, 0.f, 0.f, 0.f);

    for (int r = blockIdx.x * RPB + rl; r < M; r += gridDim.x * RPB) {
        int s0 = __ldg(off + r);
        int s1 = __ldg(off + r + 1);
        float4 acc = make_float4(0.f, 0.f, 0.f, 0.f);
        int i = s0;
        for (; i + 1 < s1; i += 2) {
            int sa = __ldg(csrc + i);
            int sb = __ldg(csrc + i + 1);
            float4 va = tmp[(size_t)sa * N4 + lane];
            float4 vb = tmp[(size_t)sb * N4 + lane];
            acc.x += va.x + vb.x;
            acc.y += va.y + vb.y;
            acc.z += va.z + vb.z;
            acc.w += va.w + vb.w;
        }
        if (i < s1) {
            int sa = __ldg(csrc + i);
            float4 va = tmp[(size_t)sa * N4 + lane];
            acc.x += va.x; acc.y += va.y; acc.z += va.z; acc.w += va.w;
        }
        float nm = norm[r];
        float4 v;
        v.x = acc.x * nm + bb.x;
        v.y = acc.y * nm + bb.y;
        v.z = acc.z * nm + bb.z;
        v.w = acc.w * nm + bb.w;
        xout[(size_t)r * N4 + lane] = v;
        if (COLSUM) {
            lsum.x += v.x; lsum.y += v.y; lsum.z += v.z; lsum.w += v.w;
        }
    }

    if (COLSUM) {
        __shared__ float scol[N4 * 4];
        if (threadIdx.x < N4 * 4) scol[threadIdx.x] = 0.0f;
        __syncthreads();
        atomicAdd(&scol[lane * 4 + 0], lsum.x);
        atomicAdd(&scol[lane * 4 + 1], lsum.y);
        atomicAdd(&scol[lane * 4 + 2], lsum.z);
        atomicAdd(&scol[lane * 4 + 3], lsum.w);
        __syncthreads();
        if (threadIdx.x < N4 * 4)
            atomicAdd(&colsum[threadIdx.x], scol[threadIdx.x]);
    }
}

// ---------------------------------------------------------------------------
// post_b: h = relu(x / sqrt(1e-6 + rowsumsq) - colsum/M). One warp per row.
// ---------------------------------------------------------------------------
template <int N>
__global__ __launch_bounds__(256) void post_b_kernel(
    const float* __restrict__ x, const float* __restrict__ colsum,
    float* __restrict__ h, int M)
{
    constexpr int PER = N / 32;
    int warp = (blockIdx.x * blockDim.x + threadIdx.x) >> 5;
    int lane = threadIdx.x & 31;
    if (warp >= M) return;

    float v[PER];
    float ss = 0.0f;
#pragma unroll
    for (int p = 0; p < PER; p++) {
        v[p] = x[(size_t)warp * N + p * 32 + lane];
        ss += v[p] * v[p];
    }
#pragma unroll
    for (int o = 16; o > 0; o >>= 1)
        ss += __shfl_xor_sync(0xffffffffu, ss, o);

    float rinv = rsqrtf(1e-6f + ss);
    float invM = 1.0f / (float)M;
#pragma unroll
    for (int p = 0; p < PER; p++) {
        float cm = colsum[p * 32 + lane] * invM;
        float o = v[p] * rinv - cm;
        h[(size_t)warp * N + p * 32 + lane] = fmaxf(o, 0.0f);
    }
}

// ---------------------------------------------------------------------------
// Launch
// ---------------------------------------------------------------------------
extern "C" void kernel_launch(void* const* d_in, const int* in_sizes, int n_in,
                              void* d_out, int out_size)
{
    const float* in_feat = (const float*)d_in[0];
    const int*   src     = (const int*)  d_in[1];
    const int*   dst     = (const int*)  d_in[2];
    const float* norm    = (const float*)d_in[3];
    const float* W1      = (const float*)d_in[4];
    const float* b1      = (const float*)d_in[5];
    const float* W2      = (const float*)d_in[6];
    const float* b2      = (const float*)d_in[7];
    const float* W3      = (const float*)d_in[8];
    const float* b3      = (const float*)d_in[9];
    float* out = (float*)d_out;

    const int M = in_sizes[3];   // 50000 nodes
    const int E = in_sizes[1];   // 800000 edges

    float *tmp, *x, *h, *colsum;
    int *deg, *off, *cur, *csrc;
    uint32_t *wth, *wtl;
    cudaGetSymbolAddress((void**)&tmp,    g_tmp);
    cudaGetSymbolAddress((void**)&x,      g_x);
    cudaGetSymbolAddress((void**)&h,      g_h);
    cudaGetSymbolAddress((void**)&colsum, g_colsum);
    cudaGetSymbolAddress((void**)&deg,    g_deg);
    cudaGetSymbolAddress((void**)&off,    g_off);
    cudaGetSymbolAddress((void**)&cur,    g_cur);
    cudaGetSymbolAddress((void**)&csrc,   g_csrc);
    cudaGetSymbolAddress((void**)&wth,    g_wth);
    cudaGetSymbolAddress((void**)&wtl,    g_wtl);

    const int gemm_blocks = (M + 127) / 128;
    const int GATHER_BLOCKS = 2048;

    // ---------------- CSR build ----------------
    cudaMemsetAsync(deg, 0, (size_t)M * sizeof(int));
    hist_kernel<<<(E + 255) / 256, 256>>>(dst, deg, E);
    scan_kernel<<<1, 1024>>>(deg, off, cur, M);
    fill_kernel<<<(E + 255) / 256, 256>>>(src, dst, cur, csrc, E);

    // ---------------- Layer 1: 256 -> 128 ----------------
    wconv_kernel<<<(256 * 128 + 255) / 256, 256>>>(
        W1, (__nv_bfloat16*)wth, (__nv_bfloat16*)wtl, 256, 128);
    gemm_tc_kernel<256, 128><<<gemm_blocks, 256>>>(
        in_feat, wth, wtl, norm, tmp, M);
    cudaMemsetAsync(colsum, 0, 128 * sizeof(float));
    gather_kernel<32, true><<<GATHER_BLOCKS, 256>>>(
        (const float4*)tmp, off, csrc, norm, b1, (float4*)x, colsum, M);
    post_b_kernel<128><<<(M + 7) / 8, 256>>>(x, colsum, h, M);

    // ---------------- Layer 2: 128 -> 128 ----------------
    wconv_kernel<<<(128 * 128 + 255) / 256, 256>>>(
        W2, (__nv_bfloat16*)wth, (__nv_bfloat16*)wtl, 128, 128);
    gemm_tc_kernel<128, 128><<<gemm_blocks, 256>>>(
        h, wth, wtl, norm, tmp, M);
    cudaMemsetAsync(colsum, 0, 128 * sizeof(float));
    gather_kernel<32, true><<<GATHER_BLOCKS, 256>>>(
        (const float4*)tmp, off, csrc, norm, b2, (float4*)x, colsum, M);
    post_b_kernel<128><<<(M + 7) / 8, 256>>>(x, colsum, h, M);

    // ---------------- Layer 3: 128 -> 64 ----------------
    wconv_kernel<<<(128 * 64 + 255) / 256, 256>>>(
        W3, (__nv_bfloat16*)wth, (__nv_bfloat16*)wtl, 128, 64);
    gemm_tc_kernel<128, 64><<<gemm_blocks, 256>>>(
        h, wth, wtl, norm, tmp, M);
    gather_kernel<16, false><<<GATHER_BLOCKS, 256>>>(
        (const float4*)tmp, off, csrc, norm, b3, (float4*)out, nullptr, M);
}

// round 4
// speedup vs baseline: 1.7992x; 1.0709x over previous
#include <cuda_runtime.h>
#include <cuda_bf16.h>
#include <cstdint>

// ---------------------------------------------------------------------------
// GCN 3-layer forward.
// Round 4: cp.async double-buffered tensor-core GEMMs (2-term bf16 split),
//          h stored as pre-split bf16 hi/lo planes, fused wconv, unrolled
//          CSR-gather aggregation.
// ---------------------------------------------------------------------------

#define NMAX 50000
#define NPAD (NMAX + 128)
#define EMAX 800000
#define FMAX 128

__device__ float g_tmp[(size_t)NMAX * FMAX];
__device__ float g_x  [(size_t)NMAX * FMAX];
__device__ float g_colsum[FMAX];
__device__ int   g_deg [NMAX];
__device__ int   g_off [NMAX + 1];
__device__ int   g_cur [NMAX];
__device__ int   g_csrc[EMAX];
// hidden activations as pre-split bf16 planes (padded rows for unguarded tiles)
__device__ __nv_bfloat16 g_hh[(size_t)NPAD * FMAX];
__device__ __nv_bfloat16 g_hl[(size_t)NPAD * FMAX];
// weights transposed + split: [n][k]
__device__ __nv_bfloat16 g_w1h[128 * 256], g_w1l[128 * 256];
__device__ __nv_bfloat16 g_w2h[128 * 128], g_w2l[128 * 128];
__device__ __nv_bfloat16 g_w3h[ 64 * 128], g_w3l[ 64 * 128];

// ---------------------------------------------------------------------------
// helpers
// ---------------------------------------------------------------------------
__device__ __forceinline__ void cp16(void* s, const void* g) {
    uint32_t sa = (uint32_t)__cvta_generic_to_shared(s);
    asm volatile("cp.async.cg.shared.global [%0], [%1], 16;\n" :: "r"(sa), "l"(g));
}
__device__ __forceinline__ void cp_commit() {
    asm volatile("cp.async.commit_group;\n");
}
__device__ __forceinline__ void mma16816(float* c, const uint32_t* a,
                                         uint32_t b0, uint32_t b1) {
    asm volatile(
        "mma.sync.aligned.m16n8k16.row.col.f32.bf16.bf16.f32 "
        "{%0,%1,%2,%3}, {%4,%5,%6,%7}, {%8,%9}, {%0,%1,%2,%3};\n"
        : "+f"(c[0]), "+f"(c[1]), "+f"(c[2]), "+f"(c[3])
        : "r"(a[0]), "r"(a[1]), "r"(a[2]), "r"(a[3]), "r"(b0), "r"(b1));
}
__device__ __forceinline__ uint32_t pack_bf2(float a, float b) {
    __nv_bfloat162 p = __halves2bfloat162(__float2bfloat16(a), __float2bfloat16(b));
    return *reinterpret_cast<uint32_t*>(&p);
}
__device__ __forceinline__ uint32_t pack_lo2(float a, float b) {
    float ha = __bfloat162float(__float2bfloat16(a));
    float hb = __bfloat162float(__float2bfloat16(b));
    __nv_bfloat162 p = __halves2bfloat162(__float2bfloat16(a - ha),
                                          __float2bfloat16(b - hb));
    return *reinterpret_cast<uint32_t*>(&p);
}

// ---------------------------------------------------------------------------
// fused W convert: 3 weights -> transposed hi/lo bf16 planes [n][k]
// ---------------------------------------------------------------------------
__global__ __launch_bounds__(256) void wconv3_kernel(
    const float* __restrict__ W1, const float* __restrict__ W2,
    const float* __restrict__ W3,
    __nv_bfloat16* __restrict__ w1h, __nv_bfloat16* __restrict__ w1l,
    __nv_bfloat16* __restrict__ w2h, __nv_bfloat16* __restrict__ w2l,
    __nv_bfloat16* __restrict__ w3h, __nv_bfloat16* __restrict__ w3l)
{
    int b = blockIdx.x;
    const float* W; __nv_bfloat16 *wh, *wl; int K, N, idx;
    if (b < 128)      { W = W1; wh = w1h; wl = w1l; K = 256; N = 128; idx = b * 256 + threadIdx.x; }
    else if (b < 192) { W = W2; wh = w2h; wl = w2l; K = 128; N = 128; idx = (b - 128) * 256 + threadIdx.x; }
    else              { W = W3; wh = w3h; wl = w3l; K = 128; N = 64;  idx = (b - 192) * 256 + threadIdx.x; }
    if (idx >= K * N) return;
    int n = idx / K, k = idx % K;
    float x = W[(size_t)k * N + n];
    __nv_bfloat16 h = __float2bfloat16(x);
    wh[idx] = h;
    wl[idx] = __float2bfloat16(x - __bfloat162float(h));
}

// ---------------------------------------------------------------------------
// Tensor-core GEMM, cp.async double-buffered.
//   C[m][n] = (sum_k A[m][k]*B[k][n]) * norm[m]
//   AF32=true : A fp32 [M][K] (register prefetch + split)
//   AF32=false: A pre-split bf16 planes [M][K] (cp.async)
//   Wt hi/lo bf16 [N][K].
// ---------------------------------------------------------------------------
extern __shared__ uint32_t dynsmem[];

template <int K, int N, bool AF32>
__global__ __launch_bounds__(256) void gemm_tc_kernel(
    const void* __restrict__ Aptr, const __nv_bfloat16* __restrict__ Alo_g,
    const __nv_bfloat16* __restrict__ wth, const __nv_bfloat16* __restrict__ wtl,
    const float* __restrict__ norm, float* __restrict__ C, int M)
{
    constexpr int BM = 128;
    constexpr int BK = 32;
    constexpr int S = 20;                 // smem row stride (words)
    constexpr int ASZ = BM * S;
    constexpr int BSZ = N * S;
    constexpr int STG = 2 * ASZ + 2 * BSZ;
    constexpr int NS = K / BK;
    constexpr int WARPS_N = (N == 128) ? 2 : 1;
    constexpr int WARPS_M = 8 / WARPS_N;
    constexpr int WM = BM / WARPS_M;
    constexpr int WN = N / WARPS_N;
    constexpr int MT = WM / 16;
    constexpr int NT = WN / 8;

    const int tid = threadIdx.x;
    const int warp = tid >> 5;
    const int lane = tid & 31;
    const int g = lane >> 2;
    const int t = lane & 3;
    const int wm = warp % WARPS_M;
    const int wn = warp / WARPS_M;
    const int row0 = blockIdx.x * BM;

    const float* Af = (const float*)Aptr;
    const __nv_bfloat16* Ahg = (const __nv_bfloat16*)Aptr;

    float acc[MT][NT][4];
#pragma unroll
    for (int i = 0; i < MT; i++)
#pragma unroll
        for (int j = 0; j < NT; j++)
#pragma unroll
            for (int q = 0; q < 4; q++) acc[i][j][q] = 0.0f;

    // ---- stage loaders ----
    auto issueB = [&](int buf, int k0) {
        uint32_t* Bh = dynsmem + buf * STG + 2 * ASZ;
        uint32_t* Bl = Bh + BSZ;
#pragma unroll
        for (int p = 0; p < N * 4 / 256; p++) {
            int idx = tid + p * 256;
            int n = idx >> 2, c = idx & 3;
            cp16(&Bh[n * S + c * 4], wth + (size_t)n * K + k0 + c * 8);
            cp16(&Bl[n * S + c * 4], wtl + (size_t)n * K + k0 + c * 8);
        }
    };
    auto issueA_bf = [&](int buf, int k0) {
        uint32_t* Ah = dynsmem + buf * STG;
        uint32_t* Al = Ah + ASZ;
#pragma unroll
        for (int p = 0; p < 2; p++) {
            int idx = tid + p * 256;
            int m = idx >> 2, c = idx & 3;
            size_t go = (size_t)(row0 + m) * K + k0 + c * 8;
            cp16(&Ah[m * S + c * 4], Ahg + go);
            cp16(&Al[m * S + c * 4], Alo_g + go);
        }
    };
    auto prefA_f32 = [&](float4* pv, int k0) {
#pragma unroll
        for (int p = 0; p < 4; p++) {
            int idx = tid + p * 256;
            int m = idx >> 3, c = idx & 7;
            int gr = row0 + m;
            pv[p] = (gr < M) ? *(const float4*)(Af + (size_t)gr * K + k0 + c * 4)
                             : make_float4(0.f, 0.f, 0.f, 0.f);
        }
    };
    auto stsA_f32 = [&](const float4* pv, int buf) {
        uint32_t* Ah = dynsmem + buf * STG;
        uint32_t* Al = Ah + ASZ;
#pragma unroll
        for (int p = 0; p < 4; p++) {
            int idx = tid + p * 256;
            int m = idx >> 3, c = idx & 7;
            int w = m * S + c * 2;
            float4 v = pv[p];
            Ah[w]     = pack_bf2(v.x, v.y);
            Ah[w + 1] = pack_bf2(v.z, v.w);
            Al[w]     = pack_lo2(v.x, v.y);
            Al[w + 1] = pack_lo2(v.z, v.w);
        }
    };
    auto compute = [&](int buf) {
        const uint32_t* Ah = dynsmem + buf * STG;
        const uint32_t* Al = Ah + ASZ;
        const uint32_t* Bh = Ah + 2 * ASZ;
        const uint32_t* Bl = Bh + BSZ;
#pragma unroll
        for (int s = 0; s < 2; s++) {
            uint32_t ah[MT][4], al[MT][4];
#pragma unroll
            for (int mt = 0; mt < MT; mt++) {
                int r0 = (wm * WM + mt * 16 + g) * S + s * 8 + t;
                int r1 = r0 + 8 * S;
                ah[mt][0] = Ah[r0];     ah[mt][1] = Ah[r1];
                ah[mt][2] = Ah[r0 + 4]; ah[mt][3] = Ah[r1 + 4];
                al[mt][0] = Al[r0];     al[mt][1] = Al[r1];
                al[mt][2] = Al[r0 + 4]; al[mt][3] = Al[r1 + 4];
            }
#pragma unroll
            for (int nt = 0; nt < NT; nt++) {
                int nb = (wn * WN + nt * 8 + g) * S + s * 8 + t;
                uint32_t bh0 = Bh[nb], bh1 = Bh[nb + 4];
                uint32_t bl0 = Bl[nb], bl1 = Bl[nb + 4];
#pragma unroll
                for (int mt = 0; mt < MT; mt++) {
                    mma16816(acc[mt][nt], ah[mt], bh0, bh1);
                    mma16816(acc[mt][nt], ah[mt], bl0, bl1);
                    mma16816(acc[mt][nt], al[mt], bh0, bh1);
                }
            }
        }
    };

    // ---- prologue: stage 0 ----
    issueB(0, 0);
    if (!AF32) {
        issueA_bf(0, 0);
        cp_commit();
    } else {
        cp_commit();
        float4 pv[4];
        prefA_f32(pv, 0);
        stsA_f32(pv, 0);
    }

    // ---- main pipeline ----
    for (int s = 0; s < NS; s++) {
        int buf = s & 1;
        float4 pv[4];
        if (s + 1 < NS) {
            if (AF32) {
                prefA_f32(pv, (s + 1) * BK);
            } else {
                issueA_bf(buf ^ 1, (s + 1) * BK);
            }
            issueB(buf ^ 1, (s + 1) * BK);
            cp_commit();
            asm volatile("cp.async.wait_group 1;\n");
        } else {
            asm volatile("cp.async.wait_group 0;\n");
        }
        __syncthreads();
        compute(buf);
        if (AF32 && s + 1 < NS) stsA_f32(pv, buf ^ 1);
        __syncthreads();
    }

    // ---- epilogue ----
#pragma unroll
    for (int mt = 0; mt < MT; mt++) {
        int r0 = row0 + wm * WM + mt * 16 + g;
        int r1 = r0 + 8;
        float nm0 = (r0 < M) ? norm[r0] : 0.0f;
        float nm1 = (r1 < M) ? norm[r1] : 0.0f;
#pragma unroll
        for (int nt = 0; nt < NT; nt++) {
            int cc = wn * WN + nt * 8 + 2 * t;
            if (r0 < M) {
                float2 o = make_float2(acc[mt][nt][0] * nm0, acc[mt][nt][1] * nm0);
                *(float2*)(C + (size_t)r0 * N + cc) = o;
            }
            if (r1 < M) {
                float2 o = make_float2(acc[mt][nt][2] * nm1, acc[mt][nt][3] * nm1);
                *(float2*)(C + (size_t)r1 * N + cc) = o;
            }
        }
    }
}

// ---------------------------------------------------------------------------
// CSR build
// ---------------------------------------------------------------------------
__global__ __launch_bounds__(256) void hist_kernel(
    const int* __restrict__ dst, int* __restrict__ deg, int E)
{
    int e = blockIdx.x * blockDim.x + threadIdx.x;
    if (e < E) atomicAdd(&deg[dst[e]], 1);
}

__global__ __launch_bounds__(1024) void scan_kernel(
    const int* __restrict__ deg, int* __restrict__ off,
    int* __restrict__ cur, int N)
{
    __shared__ int part[1024];
    const int t = threadIdx.x;
    const int chunk = (N + 1023) >> 10;
    const int start = t * chunk;
    const int end = min(start + chunk, N);

    int s = 0;
    for (int i = start; i < end; i++) s += deg[i];
    part[t] = s;
    __syncthreads();
    for (int o = 1; o < 1024; o <<= 1) {
        int v = (t >= o) ? part[t - o] : 0;
        __syncthreads();
        part[t] += v;
        __syncthreads();
    }
    int base = (t == 0) ? 0 : part[t - 1];
    for (int i = start; i < end; i++) {
        off[i] = base;
        cur[i] = base;
        base += deg[i];
    }
    if (t == 1023) off[N] = part[1023];
}

__global__ __launch_bounds__(256) void fill_kernel(
    const int* __restrict__ src, const int* __restrict__ dst,
    int* __restrict__ cur, int* __restrict__ csrc, int E)
{
    int e = blockIdx.x * blockDim.x + threadIdx.x;
    if (e >= E) return;
    int d = dst[e];
    int p = atomicAdd(&cur[d], 1);
    csrc[p] = src[e];
}

// ---------------------------------------------------------------------------
// Gather-aggregate + epilogue (unroll x4)
// ---------------------------------------------------------------------------
template <int N4, bool COLSUM>
__global__ __launch_bounds__(256) void gather_kernel(
    const float4* __restrict__ tmp, const int* __restrict__ off,
    const int* __restrict__ csrc, const float* __restrict__ norm,
    const float* __restrict__ bias, float4* __restrict__ xout,
    float* __restrict__ colsum, int M)
{
    constexpr int RPB = 256 / N4;
    const int lane = threadIdx.x % N4;
    const int rl = threadIdx.x / N4;

    float4 bb = ((const float4*)bias)[lane];
    float4 lsum = make_float4(0.f, 0.f, 0.f, 0.f);

    for (int r = blockIdx.x * RPB + rl; r < M; r += gridDim.x * RPB) {
        int s0 = __ldg(off + r);
        int s1 = __ldg(off + r + 1);
        float4 acc = make_float4(0.f, 0.f, 0.f, 0.f);
        int i = s0;
        for (; i + 3 < s1; i += 4) {
            int sa = __ldg(csrc + i);
            int sb = __ldg(csrc + i + 1);
            int sc = __ldg(csrc + i + 2);
            int sd = __ldg(csrc + i + 3);
            float4 va = tmp[(size_t)sa * N4 + lane];
            float4 vb = tmp[(size_t)sb * N4 + lane];
            float4 vc = tmp[(size_t)sc * N4 + lane];
            float4 vd = tmp[(size_t)sd * N4 + lane];
            acc.x += (va.x + vb.x) + (vc.x + vd.x);
            acc.y += (va.y + vb.y) + (vc.y + vd.y);
            acc.z += (va.z + vb.z) + (vc.z + vd.z);
            acc.w += (va.w + vb.w) + (vc.w + vd.w);
        }
        for (; i < s1; i++) {
            int sa = __ldg(csrc + i);
            float4 va = tmp[(size_t)sa * N4 + lane];
            acc.x += va.x; acc.y += va.y; acc.z += va.z; acc.w += va.w;
        }
        float nm = norm[r];
        float4 v;
        v.x = acc.x * nm + bb.x;
        v.y = acc.y * nm + bb.y;
        v.z = acc.z * nm + bb.z;
        v.w = acc.w * nm + bb.w;
        xout[(size_t)r * N4 + lane] = v;
        if (COLSUM) {
            lsum.x += v.x; lsum.y += v.y; lsum.z += v.z; lsum.w += v.w;
        }
    }

    if (COLSUM) {
        __shared__ float scol[N4 * 4];
        if (threadIdx.x < N4 * 4) scol[threadIdx.x] = 0.0f;
        __syncthreads();
        atomicAdd(&scol[lane * 4 + 0], lsum.x);
        atomicAdd(&scol[lane * 4 + 1], lsum.y);
        atomicAdd(&scol[lane * 4 + 2], lsum.z);
        atomicAdd(&scol[lane * 4 + 3], lsum.w);
        __syncthreads();
        if (threadIdx.x < N4 * 4)
            atomicAdd(&colsum[threadIdx.x], scol[threadIdx.x]);
    }
}

// ---------------------------------------------------------------------------
// post_b: h = relu(x/rownorm - colmean), emitted as bf16 hi/lo planes.
// ---------------------------------------------------------------------------
template <int N>
__global__ __launch_bounds__(256) void post_b_kernel(
    const float* __restrict__ x, const float* __restrict__ colsum,
    __nv_bfloat16* __restrict__ hh, __nv_bfloat16* __restrict__ hl, int M)
{
    constexpr int PER = N / 32;
    int warp = (blockIdx.x * blockDim.x + threadIdx.x) >> 5;
    int lane = threadIdx.x & 31;
    if (warp >= M) return;

    float v[PER];
    float ss = 0.0f;
#pragma unroll
    for (int p = 0; p < PER; p++) {
        v[p] = x[(size_t)warp * N + p * 32 + lane];
        ss += v[p] * v[p];
    }
#pragma unroll
    for (int o = 16; o > 0; o >>= 1)
        ss += __shfl_xor_sync(0xffffffffu, ss, o);

    float rinv = rsqrtf(1e-6f + ss);
    float invM = 1.0f / (float)M;
#pragma unroll
    for (int p = 0; p < PER; p++) {
        float cm = colsum[p * 32 + lane] * invM;
        float o = fmaxf(v[p] * rinv - cm, 0.0f);
        __nv_bfloat16 h = __float2bfloat16(o);
        size_t idx = (size_t)warp * N + p * 32 + lane;
        hh[idx] = h;
        hl[idx] = __float2bfloat16(o - __bfloat162float(h));
    }
}

// ---------------------------------------------------------------------------
// Launch
// ---------------------------------------------------------------------------
extern "C" void kernel_launch(void* const* d_in, const int* in_sizes, int n_in,
                              void* d_out, int out_size)
{
    const float* in_feat = (const float*)d_in[0];
    const int*   src     = (const int*)  d_in[1];
    const int*   dst     = (const int*)  d_in[2];
    const float* norm    = (const float*)d_in[3];
    const float* W1      = (const float*)d_in[4];
    const float* b1      = (const float*)d_in[5];
    const float* W2      = (const float*)d_in[6];
    const float* b2      = (const float*)d_in[7];
    const float* W3      = (const float*)d_in[8];
    const float* b3      = (const float*)d_in[9];
    float* out = (float*)d_out;

    const int M = in_sizes[3];   // 50000 nodes
    const int E = in_sizes[1];   // 800000 edges

    float *tmp, *x, *colsum;
    int *deg, *off, *cur, *csrc;
    __nv_bfloat16 *hh, *hl, *w1h, *w1l, *w2h, *w2l, *w3h, *w3l;
    cudaGetSymbolAddress((void**)&tmp,    g_tmp);
    cudaGetSymbolAddress((void**)&x,      g_x);
    cudaGetSymbolAddress((void**)&colsum, g_colsum);
    cudaGetSymbolAddress((void**)&deg,    g_deg);
    cudaGetSymbolAddress((void**)&off,    g_off);
    cudaGetSymbolAddress((void**)&cur,    g_cur);
    cudaGetSymbolAddress((void**)&csrc,   g_csrc);
    cudaGetSymbolAddress((void**)&hh,     g_hh);
    cudaGetSymbolAddress((void**)&hl,     g_hl);
    cudaGetSymbolAddress((void**)&w1h,    g_w1h);
    cudaGetSymbolAddress((void**)&w1l,    g_w1l);
    cudaGetSymbolAddress((void**)&w2h,    g_w2h);
    cudaGetSymbolAddress((void**)&w2l,    g_w2l);
    cudaGetSymbolAddress((void**)&w3h,    g_w3h);
    cudaGetSymbolAddress((void**)&w3l,    g_w3l);

    // dynamic smem limits (idempotent)
    constexpr int SMEM_128 = 2 * (2 * 128 * 20 + 2 * 128 * 20) * 4;  // 81920
    constexpr int SMEM_64  = 2 * (2 * 128 * 20 + 2 * 64  * 20) * 4;  // 61440
    cudaFuncSetAttribute(gemm_tc_kernel<256, 128, true>,
                         cudaFuncAttributeMaxDynamicSharedMemorySize, SMEM_128);
    cudaFuncSetAttribute(gemm_tc_kernel<128, 128, false>,
                         cudaFuncAttributeMaxDynamicSharedMemorySize, SMEM_128);
    cudaFuncSetAttribute(gemm_tc_kernel<128, 64, false>,
                         cudaFuncAttributeMaxDynamicSharedMemorySize, SMEM_64);

    const int gemm_blocks = (M + 127) / 128;
    const int GATHER_BLOCKS = (M + 7) / 8;

    // ---------------- CSR build + weight conversion ----------------
    cudaMemsetAsync(deg, 0, (size_t)M * sizeof(int));
    wconv3_kernel<<<224, 256>>>(W1, W2, W3, w1h, w1l, w2h, w2l, w3h, w3l);
    hist_kernel<<<(E + 255) / 256, 256>>>(dst, deg, E);
    scan_kernel<<<1, 1024>>>(deg, off, cur, M);
    fill_kernel<<<(E + 255) / 256, 256>>>(src, dst, cur, csrc, E);

    // ---------------- Layer 1: 256 -> 128 ----------------
    gemm_tc_kernel<256, 128, true><<<gemm_blocks, 256, SMEM_128>>>(
        in_feat, nullptr, w1h, w1l, norm, tmp, M);
    cudaMemsetAsync(colsum, 0, 128 * sizeof(float));
    gather_kernel<32, true><<<GATHER_BLOCKS, 256>>>(
        (const float4*)tmp, off, csrc, norm, b1, (float4*)x, colsum, M);
    post_b_kernel<128><<<(M + 7) / 8, 256>>>(x, colsum, hh, hl, M);

    // ---------------- Layer 2: 128 -> 128 ----------------
    gemm_tc_kernel<128, 128, false><<<gemm_blocks, 256, SMEM_128>>>(
        hh, hl, w2h, w2l, norm, tmp, M);
    cudaMemsetAsync(colsum, 0, 128 * sizeof(float));
    gather_kernel<32, true><<<GATHER_BLOCKS, 256>>>(
        (const float4*)tmp, off, csrc, norm, b2, (float4*)x, colsum, M);
    post_b_kernel<128><<<(M + 7) / 8, 256>>>(x, colsum, hh, hl, M);

    // ---------------- Layer 3: 128 -> 64 ----------------
    gemm_tc_kernel<128, 64, false><<<gemm_blocks, 256, SMEM_64>>>(
        hh, hl, w3h, w3l, norm, tmp, M);
    gather_kernel<16, false><<<GATHER_BLOCKS, 256>>>(
        (const float4*)tmp, off, csrc, norm, b3, (float4*)out, nullptr, M);
}

// round 6
// speedup vs baseline: 1.9364x; 1.0763x over previous
#include <cuda_runtime.h>
#include <cuda_bf16.h>
#include <cstdint>

// ---------------------------------------------------------------------------
// GCN 3-layer forward.
// Round 5 (resubmit after infra failure): post_b eliminated (rownorm fused
// into gather via warp-reduce, relu(y - colmean) fused into next GEMM's
// A-load), CSR build unrolled x4, deg-zero folded into wconv, dual colsum
// buffers. GEMMs: cp.async double-buffered tensor-core, 2-term bf16 split.
// ---------------------------------------------------------------------------

#define NMAX 50000
#define EMAX 800000
#define FMAX 128

__device__ float g_tmp[(size_t)NMAX * FMAX];
__device__ float g_y  [(size_t)NMAX * FMAX];   // pairnorm-scaled activations
__device__ float g_colsumA[FMAX];
__device__ float g_colsumB[FMAX];
__device__ int   g_deg [NMAX];
__device__ int   g_off [NMAX + 1];
__device__ int   g_cur [NMAX];
__device__ int   g_csrc[EMAX];
// weights transposed + split: [n][k]
__device__ __nv_bfloat16 g_w1h[128 * 256], g_w1l[128 * 256];
__device__ __nv_bfloat16 g_w2h[128 * 128], g_w2l[128 * 128];
__device__ __nv_bfloat16 g_w3h[ 64 * 128], g_w3l[ 64 * 128];

// ---------------------------------------------------------------------------
// helpers
// ---------------------------------------------------------------------------
__device__ __forceinline__ void cp16(void* s, const void* g) {
    uint32_t sa = (uint32_t)__cvta_generic_to_shared(s);
    asm volatile("cp.async.cg.shared.global [%0], [%1], 16;\n" :: "r"(sa), "l"(g));
}
__device__ __forceinline__ void cp_commit() {
    asm volatile("cp.async.commit_group;\n");
}
__device__ __forceinline__ void mma16816(float* c, const uint32_t* a,
                                         uint32_t b0, uint32_t b1) {
    asm volatile(
        "mma.sync.aligned.m16n8k16.row.col.f32.bf16.bf16.f32 "
        "{%0,%1,%2,%3}, {%4,%5,%6,%7}, {%8,%9}, {%0,%1,%2,%3};\n"
        : "+f"(c[0]), "+f"(c[1]), "+f"(c[2]), "+f"(c[3])
        : "r"(a[0]), "r"(a[1]), "r"(a[2]), "r"(a[3]), "r"(b0), "r"(b1));
}
__device__ __forceinline__ uint32_t pack_bf2(float a, float b) {
    __nv_bfloat162 p = __halves2bfloat162(__float2bfloat16(a), __float2bfloat16(b));
    return *reinterpret_cast<uint32_t*>(&p);
}
__device__ __forceinline__ uint32_t pack_lo2(float a, float b) {
    float ha = __bfloat162float(__float2bfloat16(a));
    float hb = __bfloat162float(__float2bfloat16(b));
    __nv_bfloat162 p = __halves2bfloat162(__float2bfloat16(a - ha),
                                          __float2bfloat16(b - hb));
    return *reinterpret_cast<uint32_t*>(&p);
}

// ---------------------------------------------------------------------------
// fused W convert (3 weights -> transposed hi/lo planes) + deg zeroing
// ---------------------------------------------------------------------------
__global__ __launch_bounds__(256) void wconv3_kernel(
    const float* __restrict__ W1, const float* __restrict__ W2,
    const float* __restrict__ W3,
    __nv_bfloat16* __restrict__ w1h, __nv_bfloat16* __restrict__ w1l,
    __nv_bfloat16* __restrict__ w2h, __nv_bfloat16* __restrict__ w2l,
    __nv_bfloat16* __restrict__ w3h, __nv_bfloat16* __restrict__ w3l,
    int* __restrict__ deg, int M)
{
    int gtid = blockIdx.x * 256 + threadIdx.x;
    if (gtid < M) deg[gtid] = 0;

    int b = blockIdx.x;
    const float* W; __nv_bfloat16 *wh, *wl; int K, N, idx;
    if (b < 128)      { W = W1; wh = w1h; wl = w1l; K = 256; N = 128; idx = b * 256 + threadIdx.x; }
    else if (b < 192) { W = W2; wh = w2h; wl = w2l; K = 128; N = 128; idx = (b - 128) * 256 + threadIdx.x; }
    else              { W = W3; wh = w3h; wl = w3l; K = 128; N = 64;  idx = (b - 192) * 256 + threadIdx.x; }
    if (idx >= K * N) return;
    int n = idx / K, k = idx % K;
    float x = W[(size_t)k * N + n];
    __nv_bfloat16 h = __float2bfloat16(x);
    wh[idx] = h;
    wl[idx] = __float2bfloat16(x - __bfloat162float(h));
}

// ---------------------------------------------------------------------------
// Tensor-core GEMM, cp.async double-buffered (B), register-prefetch A (fp32).
//   RELUCM: A_elem = relu(y[m][k] - colmean[k])  (pairnorm tail of prev layer)
//   C[m][n] = (sum_k A*B) * norm[m].  colsum_zero: zeroed by block 0 for the
//   FOLLOWING gather (safe: that gather launches after this kernel ends).
// ---------------------------------------------------------------------------
extern __shared__ uint32_t dynsmem[];

template <int K, int N, bool RELUCM>
__global__ __launch_bounds__(256) void gemm_tc_kernel(
    const float* __restrict__ A, const float* __restrict__ cmean_in,
    float invM, const __nv_bfloat16* __restrict__ wth,
    const __nv_bfloat16* __restrict__ wtl, const float* __restrict__ norm,
    float* __restrict__ C, int M, float* __restrict__ colsum_zero)
{
    constexpr int BM = 128;
    constexpr int BK = 32;
    constexpr int S = 20;
    constexpr int ASZ = BM * S;
    constexpr int BSZ = N * S;
    constexpr int STG = 2 * ASZ + 2 * BSZ;
    constexpr int NS = K / BK;
    constexpr int WARPS_N = (N == 128) ? 2 : 1;
    constexpr int WARPS_M = 8 / WARPS_N;
    constexpr int WM = BM / WARPS_M;
    constexpr int WN = N / WARPS_N;
    constexpr int MT = WM / 16;
    constexpr int NT = WN / 8;

    const int tid = threadIdx.x;
    const int warp = tid >> 5;
    const int lane = tid & 31;
    const int g = lane >> 2;
    const int t = lane & 3;
    const int wm = warp % WARPS_M;
    const int wn = warp / WARPS_M;
    const int row0 = blockIdx.x * BM;

    if (colsum_zero && blockIdx.x == 0 && tid < FMAX) colsum_zero[tid] = 0.0f;

    float acc[MT][NT][4];
#pragma unroll
    for (int i = 0; i < MT; i++)
#pragma unroll
        for (int j = 0; j < NT; j++)
#pragma unroll
            for (int q = 0; q < 4; q++) acc[i][j][q] = 0.0f;

    auto issueB = [&](int buf, int k0) {
        uint32_t* Bh = dynsmem + buf * STG + 2 * ASZ;
        uint32_t* Bl = Bh + BSZ;
#pragma unroll
        for (int p = 0; p < N * 4 / 256; p++) {
            int idx = tid + p * 256;
            int n = idx >> 2, c = idx & 3;
            cp16(&Bh[n * S + c * 4], wth + (size_t)n * K + k0 + c * 8);
            cp16(&Bl[n * S + c * 4], wtl + (size_t)n * K + k0 + c * 8);
        }
    };
    auto prefA = [&](float4* pv, int k0) {
#pragma unroll
        for (int p = 0; p < 4; p++) {
            int idx = tid + p * 256;
            int m = idx >> 3, c = idx & 7;
            int gr = row0 + m;
            float4 v = make_float4(0.f, 0.f, 0.f, 0.f);
            if (gr < M) {
                v = *(const float4*)(A + (size_t)gr * K + k0 + c * 4);
                if (RELUCM) {
                    const float4 cs = *(const float4*)(cmean_in + k0 + c * 4);
                    v.x = fmaxf(v.x - cs.x * invM, 0.0f);
                    v.y = fmaxf(v.y - cs.y * invM, 0.0f);
                    v.z = fmaxf(v.z - cs.z * invM, 0.0f);
                    v.w = fmaxf(v.w - cs.w * invM, 0.0f);
                }
            }
            pv[p] = v;
        }
    };
    auto stsA = [&](const float4* pv, int buf) {
        uint32_t* Ah = dynsmem + buf * STG;
        uint32_t* Al = Ah + ASZ;
#pragma unroll
        for (int p = 0; p < 4; p++) {
            int idx = tid + p * 256;
            int m = idx >> 3, c = idx & 7;
            int w = m * S + c * 2;
            float4 v = pv[p];
            Ah[w]     = pack_bf2(v.x, v.y);
            Ah[w + 1] = pack_bf2(v.z, v.w);
            Al[w]     = pack_lo2(v.x, v.y);
            Al[w + 1] = pack_lo2(v.z, v.w);
        }
    };
    auto compute = [&](int buf) {
        const uint32_t* Ah = dynsmem + buf * STG;
        const uint32_t* Al = Ah + ASZ;
        const uint32_t* Bh = Ah + 2 * ASZ;
        const uint32_t* Bl = Bh + BSZ;
#pragma unroll
        for (int s = 0; s < 2; s++) {
            uint32_t ah[MT][4], al[MT][4];
#pragma unroll
            for (int mt = 0; mt < MT; mt++) {
                int r0 = (wm * WM + mt * 16 + g) * S + s * 8 + t;
                int r1 = r0 + 8 * S;
                ah[mt][0] = Ah[r0];     ah[mt][1] = Ah[r1];
                ah[mt][2] = Ah[r0 + 4]; ah[mt][3] = Ah[r1 + 4];
                al[mt][0] = Al[r0];     al[mt][1] = Al[r1];
                al[mt][2] = Al[r0 + 4]; al[mt][3] = Al[r1 + 4];
            }
#pragma unroll
            for (int nt = 0; nt < NT; nt++) {
                int nb = (wn * WN + nt * 8 + g) * S + s * 8 + t;
                uint32_t bh0 = Bh[nb], bh1 = Bh[nb + 4];
                uint32_t bl0 = Bl[nb], bl1 = Bl[nb + 4];
#pragma unroll
                for (int mt = 0; mt < MT; mt++) {
                    mma16816(acc[mt][nt], ah[mt], bh0, bh1);
                    mma16816(acc[mt][nt], ah[mt], bl0, bl1);
                    mma16816(acc[mt][nt], al[mt], bh0, bh1);
                }
            }
        }
    };

    // prologue
    issueB(0, 0);
    cp_commit();
    {
        float4 pv[4];
        prefA(pv, 0);
        stsA(pv, 0);
    }

    for (int s = 0; s < NS; s++) {
        int buf = s & 1;
        float4 pv[4];
        if (s + 1 < NS) {
            prefA(pv, (s + 1) * BK);
            issueB(buf ^ 1, (s + 1) * BK);
            cp_commit();
            asm volatile("cp.async.wait_group 1;\n");
        } else {
            asm volatile("cp.async.wait_group 0;\n");
        }
        __syncthreads();
        compute(buf);
        if (s + 1 < NS) stsA(pv, buf ^ 1);
        __syncthreads();
    }

#pragma unroll
    for (int mt = 0; mt < MT; mt++) {
        int r0 = row0 + wm * WM + mt * 16 + g;
        int r1 = r0 + 8;
        float nm0 = (r0 < M) ? norm[r0] : 0.0f;
        float nm1 = (r1 < M) ? norm[r1] : 0.0f;
#pragma unroll
        for (int nt = 0; nt < NT; nt++) {
            int cc = wn * WN + nt * 8 + 2 * t;
            if (r0 < M) {
                float2 o = make_float2(acc[mt][nt][0] * nm0, acc[mt][nt][1] * nm0);
                *(float2*)(C + (size_t)r0 * N + cc) = o;
            }
            if (r1 < M) {
                float2 o = make_float2(acc[mt][nt][2] * nm1, acc[mt][nt][3] * nm1);
                *(float2*)(C + (size_t)r1 * N + cc) = o;
            }
        }
    }
}

// ---------------------------------------------------------------------------
// CSR build (x4 unrolled, int4 edge loads)
// ---------------------------------------------------------------------------
__global__ __launch_bounds__(256) void hist_kernel(
    const int* __restrict__ dst, int* __restrict__ deg, int E)
{
    int e = (blockIdx.x * blockDim.x + threadIdx.x) * 4;
    if (e + 3 < E) {
        int4 d = *(const int4*)(dst + e);
        atomicAdd(&deg[d.x], 1);
        atomicAdd(&deg[d.y], 1);
        atomicAdd(&deg[d.z], 1);
        atomicAdd(&deg[d.w], 1);
    } else {
        for (int j = e; j < E; j++) atomicAdd(&deg[dst[j]], 1);
    }
}

__global__ __launch_bounds__(1024) void scan_kernel(
    const int* __restrict__ deg, int* __restrict__ off,
    int* __restrict__ cur, int N)
{
    __shared__ int part[1024];
    const int t = threadIdx.x;
    const int chunk = (N + 1023) >> 10;
    const int start = t * chunk;
    const int end = min(start + chunk, N);

    int s = 0;
    for (int i = start; i < end; i++) s += deg[i];
    part[t] = s;
    __syncthreads();
    for (int o = 1; o < 1024; o <<= 1) {
        int v = (t >= o) ? part[t - o] : 0;
        __syncthreads();
        part[t] += v;
        __syncthreads();
    }
    int base = (t == 0) ? 0 : part[t - 1];
    for (int i = start; i < end; i++) {
        off[i] = base;
        cur[i] = base;
        base += deg[i];
    }
    if (t == 1023) off[N] = part[1023];
}

__global__ __launch_bounds__(256) void fill_kernel(
    const int* __restrict__ src, const int* __restrict__ dst,
    int* __restrict__ cur, int* __restrict__ csrc, int E)
{
    int e = (blockIdx.x * blockDim.x + threadIdx.x) * 4;
    if (e + 3 < E) {
        int4 s = *(const int4*)(src + e);
        int4 d = *(const int4*)(dst + e);
        csrc[atomicAdd(&cur[d.x], 1)] = s.x;
        csrc[atomicAdd(&cur[d.y], 1)] = s.y;
        csrc[atomicAdd(&cur[d.z], 1)] = s.z;
        csrc[atomicAdd(&cur[d.w], 1)] = s.w;
    } else {
        for (int j = e; j < E; j++)
            csrc[atomicAdd(&cur[dst[j]], 1)] = src[j];
    }
}

// ---------------------------------------------------------------------------
// Gather-aggregate.
//   PAIRNORM=1 (N4=32, warp per row): v = acc*norm + b; colsum += v;
//       ss = warp-reduce(v.v); write y = v * rsqrt(1e-6+ss).
//   PAIRNORM=0: write v directly (final layer).
// ---------------------------------------------------------------------------
template <int N4, bool PAIRNORM>
__global__ __launch_bounds__(256) void gather_kernel(
    const float4* __restrict__ tmp, const int* __restrict__ off,
    const int* __restrict__ csrc, const float* __restrict__ norm,
    const float* __restrict__ bias, float4* __restrict__ xout,
    float* __restrict__ colsum, int M)
{
    constexpr int RPB = 256 / N4;
    const int lane = threadIdx.x % N4;
    const int rl = threadIdx.x / N4;

    float4 bb = ((const float4*)bias)[lane];
    float4 lsum = make_float4(0.f, 0.f, 0.f, 0.f);

    for (int r = blockIdx.x * RPB + rl; r < M; r += gridDim.x * RPB) {
        int s0 = __ldg(off + r);
        int s1 = __ldg(off + r + 1);
        float4 acc = make_float4(0.f, 0.f, 0.f, 0.f);
        int i = s0;
        for (; i + 3 < s1; i += 4) {
            int sa = __ldg(csrc + i);
            int sb = __ldg(csrc + i + 1);
            int sc = __ldg(csrc + i + 2);
            int sd = __ldg(csrc + i + 3);
            float4 va = tmp[(size_t)sa * N4 + lane];
            float4 vb = tmp[(size_t)sb * N4 + lane];
            float4 vc = tmp[(size_t)sc * N4 + lane];
            float4 vd = tmp[(size_t)sd * N4 + lane];
            acc.x += (va.x + vb.x) + (vc.x + vd.x);
            acc.y += (va.y + vb.y) + (vc.y + vd.y);
            acc.z += (va.z + vb.z) + (vc.z + vd.z);
            acc.w += (va.w + vb.w) + (vc.w + vd.w);
        }
        for (; i < s1; i++) {
            int sa = __ldg(csrc + i);
            float4 va = tmp[(size_t)sa * N4 + lane];
            acc.x += va.x; acc.y += va.y; acc.z += va.z; acc.w += va.w;
        }
        float nm = norm[r];
        float4 v;
        v.x = acc.x * nm + bb.x;
        v.y = acc.y * nm + bb.y;
        v.z = acc.z * nm + bb.z;
        v.w = acc.w * nm + bb.w;
        if (PAIRNORM) {
            lsum.x += v.x; lsum.y += v.y; lsum.z += v.z; lsum.w += v.w;
            float ss = v.x * v.x + v.y * v.y + v.z * v.z + v.w * v.w;
#pragma unroll
            for (int o = 16; o > 0; o >>= 1)
                ss += __shfl_xor_sync(0xffffffffu, ss, o);
            float rinv = rsqrtf(1e-6f + ss);
            v.x *= rinv; v.y *= rinv; v.z *= rinv; v.w *= rinv;
        }
        xout[(size_t)r * N4 + lane] = v;
    }

    if (PAIRNORM) {
        __shared__ float scol[N4 * 4];
        if (threadIdx.x < N4 * 4) scol[threadIdx.x] = 0.0f;
        __syncthreads();
        atomicAdd(&scol[lane * 4 + 0], lsum.x);
        atomicAdd(&scol[lane * 4 + 1], lsum.y);
        atomicAdd(&scol[lane * 4 + 2], lsum.z);
        atomicAdd(&scol[lane * 4 + 3], lsum.w);
        __syncthreads();
        if (threadIdx.x < N4 * 4)
            atomicAdd(&colsum[threadIdx.x], scol[threadIdx.x]);
    }
}

// ---------------------------------------------------------------------------
// Launch
// ---------------------------------------------------------------------------
extern "C" void kernel_launch(void* const* d_in, const int* in_sizes, int n_in,
                              void* d_out, int out_size)
{
    const float* in_feat = (const float*)d_in[0];
    const int*   src     = (const int*)  d_in[1];
    const int*   dst     = (const int*)  d_in[2];
    const float* norm    = (const float*)d_in[3];
    const float* W1      = (const float*)d_in[4];
    const float* b1      = (const float*)d_in[5];
    const float* W2      = (const float*)d_in[6];
    const float* b2      = (const float*)d_in[7];
    const float* W3      = (const float*)d_in[8];
    const float* b3      = (const float*)d_in[9];
    float* out = (float*)d_out;

    const int M = in_sizes[3];   // 50000 nodes
    const int E = in_sizes[1];   // 800000 edges
    const float invM = 1.0f / (float)M;

    float *tmp, *y, *colsumA, *colsumB;
    int *deg, *off, *cur, *csrc;
    __nv_bfloat16 *w1h, *w1l, *w2h, *w2l, *w3h, *w3l;
    cudaGetSymbolAddress((void**)&tmp,     g_tmp);
    cudaGetSymbolAddress((void**)&y,       g_y);
    cudaGetSymbolAddress((void**)&colsumA, g_colsumA);
    cudaGetSymbolAddress((void**)&colsumB, g_colsumB);
    cudaGetSymbolAddress((void**)&deg,     g_deg);
    cudaGetSymbolAddress((void**)&off,     g_off);
    cudaGetSymbolAddress((void**)&cur,     g_cur);
    cudaGetSymbolAddress((void**)&csrc,    g_csrc);
    cudaGetSymbolAddress((void**)&w1h,     g_w1h);
    cudaGetSymbolAddress((void**)&w1l,     g_w1l);
    cudaGetSymbolAddress((void**)&w2h,     g_w2h);
    cudaGetSymbolAddress((void**)&w2l,     g_w2l);
    cudaGetSymbolAddress((void**)&w3h,     g_w3h);
    cudaGetSymbolAddress((void**)&w3l,     g_w3l);

    constexpr int SMEM_128 = 2 * (2 * 128 * 20 + 2 * 128 * 20) * 4;  // 81920
    constexpr int SMEM_64  = 2 * (2 * 128 * 20 + 2 * 64  * 20) * 4;  // 61440
    cudaFuncSetAttribute(gemm_tc_kernel<256, 128, false>,
                         cudaFuncAttributeMaxDynamicSharedMemorySize, SMEM_128);
    cudaFuncSetAttribute(gemm_tc_kernel<128, 128, true>,
                         cudaFuncAttributeMaxDynamicSharedMemorySize, SMEM_128);
    cudaFuncSetAttribute(gemm_tc_kernel<128, 64, true>,
                         cudaFuncAttributeMaxDynamicSharedMemorySize, SMEM_64);

    const int gemm_blocks = (M + 127) / 128;
    const int GATHER_BLOCKS = (M + 7) / 8;
    const int GATHER_BLOCKS3 = (M + 15) / 16;
    const int E4_BLOCKS = ((E + 3) / 4 + 255) / 256;

    // ---------------- CSR build + weight conversion ----------------
    wconv3_kernel<<<224, 256>>>(W1, W2, W3, w1h, w1l, w2h, w2l, w3h, w3l,
                                deg, M);
    hist_kernel<<<E4_BLOCKS, 256>>>(dst, deg, E);
    scan_kernel<<<1, 1024>>>(deg, off, cur, M);
    fill_kernel<<<E4_BLOCKS, 256>>>(src, dst, cur, csrc, E);

    // ---------------- Layer 1: 256 -> 128 ----------------
    gemm_tc_kernel<256, 128, false><<<gemm_blocks, 256, SMEM_128>>>(
        in_feat, nullptr, 0.0f, w1h, w1l, norm, tmp, M, colsumA);
    gather_kernel<32, true><<<GATHER_BLOCKS, 256>>>(
        (const float4*)tmp, off, csrc, norm, b1, (float4*)y, colsumA, M);

    // ---------------- Layer 2: 128 -> 128 ----------------
    gemm_tc_kernel<128, 128, true><<<gemm_blocks, 256, SMEM_128>>>(
        y, colsumA, invM, w2h, w2l, norm, tmp, M, colsumB);
    gather_kernel<32, true><<<GATHER_BLOCKS, 256>>>(
        (const float4*)tmp, off, csrc, norm, b2, (float4*)y, colsumB, M);

    // ---------------- Layer 3: 128 -> 64 ----------------
    gemm_tc_kernel<128, 64, true><<<gemm_blocks, 256, SMEM_64>>>(
        y, colsumB, invM, w3h, w3l, norm, tmp, M, nullptr);
    gather_kernel<16, false><<<GATHER_BLOCKS3, 256>>>(
        (const float4*)tmp, off, csrc, norm, b3, (float4*)out, nullptr, M);
}

// round 7
// speedup vs baseline: 2.1999x; 1.1361x over previous
#include <cuda_runtime.h>
#include <cuda_bf16.h>
#include <cstdint>

// ---------------------------------------------------------------------------
// GCN 3-layer forward.
// Round 7: CSR build runs on a side stream, overlapped with wconv+gemm1 via
// graph-capture fork-join (events). fill/hist unrolled x8. Everything else
// as round 5: fused pairnorm (gather does rownorm, next GEMM does
// relu(y-colmean)), cp.async double-buffered tensor-core GEMMs with 2-term
// bf16 split.
// ---------------------------------------------------------------------------

#define NMAX 50000
#define EMAX 800000
#define FMAX 128

__device__ float g_tmp[(size_t)NMAX * FMAX];
__device__ float g_y  [(size_t)NMAX * FMAX];
__device__ float g_colsumA[FMAX];
__device__ float g_colsumB[FMAX];
__device__ int   g_deg [NMAX];
__device__ int   g_off [NMAX + 1];
__device__ int   g_cur [NMAX];
__device__ int   g_csrc[EMAX];
__device__ __nv_bfloat16 g_w1h[128 * 256], g_w1l[128 * 256];
__device__ __nv_bfloat16 g_w2h[128 * 128], g_w2l[128 * 128];
__device__ __nv_bfloat16 g_w3h[ 64 * 128], g_w3l[ 64 * 128];

// ---------------------------------------------------------------------------
// helpers
// ---------------------------------------------------------------------------
__device__ __forceinline__ void cp16(void* s, const void* g) {
    uint32_t sa = (uint32_t)__cvta_generic_to_shared(s);
    asm volatile("cp.async.cg.shared.global [%0], [%1], 16;\n" :: "r"(sa), "l"(g));
}
__device__ __forceinline__ void cp_commit() {
    asm volatile("cp.async.commit_group;\n");
}
__device__ __forceinline__ void mma16816(float* c, const uint32_t* a,
                                         uint32_t b0, uint32_t b1) {
    asm volatile(
        "mma.sync.aligned.m16n8k16.row.col.f32.bf16.bf16.f32 "
        "{%0,%1,%2,%3}, {%4,%5,%6,%7}, {%8,%9}, {%0,%1,%2,%3};\n"
        : "+f"(c[0]), "+f"(c[1]), "+f"(c[2]), "+f"(c[3])
        : "r"(a[0]), "r"(a[1]), "r"(a[2]), "r"(a[3]), "r"(b0), "r"(b1));
}
__device__ __forceinline__ uint32_t pack_bf2(float a, float b) {
    __nv_bfloat162 p = __halves2bfloat162(__float2bfloat16(a), __float2bfloat16(b));
    return *reinterpret_cast<uint32_t*>(&p);
}
__device__ __forceinline__ uint32_t pack_lo2(float a, float b) {
    float ha = __bfloat162float(__float2bfloat16(a));
    float hb = __bfloat162float(__float2bfloat16(b));
    __nv_bfloat162 p = __halves2bfloat162(__float2bfloat16(a - ha),
                                          __float2bfloat16(b - hb));
    return *reinterpret_cast<uint32_t*>(&p);
}

// ---------------------------------------------------------------------------
// fused W convert (3 weights -> transposed hi/lo planes)
// ---------------------------------------------------------------------------
__global__ __launch_bounds__(256) void wconv3_kernel(
    const float* __restrict__ W1, const float* __restrict__ W2,
    const float* __restrict__ W3,
    __nv_bfloat16* __restrict__ w1h, __nv_bfloat16* __restrict__ w1l,
    __nv_bfloat16* __restrict__ w2h, __nv_bfloat16* __restrict__ w2l,
    __nv_bfloat16* __restrict__ w3h, __nv_bfloat16* __restrict__ w3l)
{
    int b = blockIdx.x;
    const float* W; __nv_bfloat16 *wh, *wl; int K, N, idx;
    if (b < 128)      { W = W1; wh = w1h; wl = w1l; K = 256; N = 128; idx = b * 256 + threadIdx.x; }
    else if (b < 192) { W = W2; wh = w2h; wl = w2l; K = 128; N = 128; idx = (b - 128) * 256 + threadIdx.x; }
    else              { W = W3; wh = w3h; wl = w3l; K = 128; N = 64;  idx = (b - 192) * 256 + threadIdx.x; }
    if (idx >= K * N) return;
    int n = idx / K, k = idx % K;
    float x = W[(size_t)k * N + n];
    __nv_bfloat16 h = __float2bfloat16(x);
    wh[idx] = h;
    wl[idx] = __float2bfloat16(x - __bfloat162float(h));
}

// ---------------------------------------------------------------------------
// Tensor-core GEMM, cp.async double-buffered (B), register-prefetch A (fp32).
// ---------------------------------------------------------------------------
extern __shared__ uint32_t dynsmem[];

template <int K, int N, bool RELUCM>
__global__ __launch_bounds__(256) void gemm_tc_kernel(
    const float* __restrict__ A, const float* __restrict__ cmean_in,
    float invM, const __nv_bfloat16* __restrict__ wth,
    const __nv_bfloat16* __restrict__ wtl, const float* __restrict__ norm,
    float* __restrict__ C, int M, float* __restrict__ colsum_zero)
{
    constexpr int BM = 128;
    constexpr int BK = 32;
    constexpr int S = 20;
    constexpr int ASZ = BM * S;
    constexpr int BSZ = N * S;
    constexpr int STG = 2 * ASZ + 2 * BSZ;
    constexpr int NS = K / BK;
    constexpr int WARPS_N = (N == 128) ? 2 : 1;
    constexpr int WARPS_M = 8 / WARPS_N;
    constexpr int WM = BM / WARPS_M;
    constexpr int WN = N / WARPS_N;
    constexpr int MT = WM / 16;
    constexpr int NT = WN / 8;

    const int tid = threadIdx.x;
    const int warp = tid >> 5;
    const int lane = tid & 31;
    const int g = lane >> 2;
    const int t = lane & 3;
    const int wm = warp % WARPS_M;
    const int wn = warp / WARPS_M;
    const int row0 = blockIdx.x * BM;

    if (colsum_zero && blockIdx.x == 0 && tid < FMAX) colsum_zero[tid] = 0.0f;

    float acc[MT][NT][4];
#pragma unroll
    for (int i = 0; i < MT; i++)
#pragma unroll
        for (int j = 0; j < NT; j++)
#pragma unroll
            for (int q = 0; q < 4; q++) acc[i][j][q] = 0.0f;

    auto issueB = [&](int buf, int k0) {
        uint32_t* Bh = dynsmem + buf * STG + 2 * ASZ;
        uint32_t* Bl = Bh + BSZ;
#pragma unroll
        for (int p = 0; p < N * 4 / 256; p++) {
            int idx = tid + p * 256;
            int n = idx >> 2, c = idx & 3;
            cp16(&Bh[n * S + c * 4], wth + (size_t)n * K + k0 + c * 8);
            cp16(&Bl[n * S + c * 4], wtl + (size_t)n * K + k0 + c * 8);
        }
    };
    auto prefA = [&](float4* pv, int k0) {
#pragma unroll
        for (int p = 0; p < 4; p++) {
            int idx = tid + p * 256;
            int m = idx >> 3, c = idx & 7;
            int gr = row0 + m;
            float4 v = make_float4(0.f, 0.f, 0.f, 0.f);
            if (gr < M) {
                v = *(const float4*)(A + (size_t)gr * K + k0 + c * 4);
                if (RELUCM) {
                    const float4 cs = *(const float4*)(cmean_in + k0 + c * 4);
                    v.x = fmaxf(v.x - cs.x * invM, 0.0f);
                    v.y = fmaxf(v.y - cs.y * invM, 0.0f);
                    v.z = fmaxf(v.z - cs.z * invM, 0.0f);
                    v.w = fmaxf(v.w - cs.w * invM, 0.0f);
                }
            }
            pv[p] = v;
        }
    };
    auto stsA = [&](const float4* pv, int buf) {
        uint32_t* Ah = dynsmem + buf * STG;
        uint32_t* Al = Ah + ASZ;
#pragma unroll
        for (int p = 0; p < 4; p++) {
            int idx = tid + p * 256;
            int m = idx >> 3, c = idx & 7;
            int w = m * S + c * 2;
            float4 v = pv[p];
            Ah[w]     = pack_bf2(v.x, v.y);
            Ah[w + 1] = pack_bf2(v.z, v.w);
            Al[w]     = pack_lo2(v.x, v.y);
            Al[w + 1] = pack_lo2(v.z, v.w);
        }
    };
    auto compute = [&](int buf) {
        const uint32_t* Ah = dynsmem + buf * STG;
        const uint32_t* Al = Ah + ASZ;
        const uint32_t* Bh = Ah + 2 * ASZ;
        const uint32_t* Bl = Bh + BSZ;
#pragma unroll
        for (int s = 0; s < 2; s++) {
            uint32_t ah[MT][4], al[MT][4];
#pragma unroll
            for (int mt = 0; mt < MT; mt++) {
                int r0 = (wm * WM + mt * 16 + g) * S + s * 8 + t;
                int r1 = r0 + 8 * S;
                ah[mt][0] = Ah[r0];     ah[mt][1] = Ah[r1];
                ah[mt][2] = Ah[r0 + 4]; ah[mt][3] = Ah[r1 + 4];
                al[mt][0] = Al[r0];     al[mt][1] = Al[r1];
                al[mt][2] = Al[r0 + 4]; al[mt][3] = Al[r1 + 4];
            }
#pragma unroll
            for (int nt = 0; nt < NT; nt++) {
                int nb = (wn * WN + nt * 8 + g) * S + s * 8 + t;
                uint32_t bh0 = Bh[nb], bh1 = Bh[nb + 4];
                uint32_t bl0 = Bl[nb], bl1 = Bl[nb + 4];
#pragma unroll
                for (int mt = 0; mt < MT; mt++) {
                    mma16816(acc[mt][nt], ah[mt], bh0, bh1);
                    mma16816(acc[mt][nt], ah[mt], bl0, bl1);
                    mma16816(acc[mt][nt], al[mt], bh0, bh1);
                }
            }
        }
    };

    issueB(0, 0);
    cp_commit();
    {
        float4 pv[4];
        prefA(pv, 0);
        stsA(pv, 0);
    }

    for (int s = 0; s < NS; s++) {
        int buf = s & 1;
        float4 pv[4];
        if (s + 1 < NS) {
            prefA(pv, (s + 1) * BK);
            issueB(buf ^ 1, (s + 1) * BK);
            cp_commit();
            asm volatile("cp.async.wait_group 1;\n");
        } else {
            asm volatile("cp.async.wait_group 0;\n");
        }
        __syncthreads();
        compute(buf);
        if (s + 1 < NS) stsA(pv, buf ^ 1);
        __syncthreads();
    }

#pragma unroll
    for (int mt = 0; mt < MT; mt++) {
        int r0 = row0 + wm * WM + mt * 16 + g;
        int r1 = r0 + 8;
        float nm0 = (r0 < M) ? norm[r0] : 0.0f;
        float nm1 = (r1 < M) ? norm[r1] : 0.0f;
#pragma unroll
        for (int nt = 0; nt < NT; nt++) {
            int cc = wn * WN + nt * 8 + 2 * t;
            if (r0 < M) {
                float2 o = make_float2(acc[mt][nt][0] * nm0, acc[mt][nt][1] * nm0);
                *(float2*)(C + (size_t)r0 * N + cc) = o;
            }
            if (r1 < M) {
                float2 o = make_float2(acc[mt][nt][2] * nm1, acc[mt][nt][3] * nm1);
                *(float2*)(C + (size_t)r1 * N + cc) = o;
            }
        }
    }
}

// ---------------------------------------------------------------------------
// CSR build (x8 unrolled)
// ---------------------------------------------------------------------------
__global__ __launch_bounds__(256) void hist_kernel(
    const int* __restrict__ dst, int* __restrict__ deg, int E)
{
    int e = (blockIdx.x * blockDim.x + threadIdx.x) * 8;
    if (e + 7 < E) {
        int4 d0 = *(const int4*)(dst + e);
        int4 d1 = *(const int4*)(dst + e + 4);
        atomicAdd(&deg[d0.x], 1); atomicAdd(&deg[d0.y], 1);
        atomicAdd(&deg[d0.z], 1); atomicAdd(&deg[d0.w], 1);
        atomicAdd(&deg[d1.x], 1); atomicAdd(&deg[d1.y], 1);
        atomicAdd(&deg[d1.z], 1); atomicAdd(&deg[d1.w], 1);
    } else {
        for (int j = e; j < E; j++) atomicAdd(&deg[dst[j]], 1);
    }
}

__global__ __launch_bounds__(1024) void scan_kernel(
    const int* __restrict__ deg, int* __restrict__ off,
    int* __restrict__ cur, int N)
{
    __shared__ int part[1024];
    const int t = threadIdx.x;
    const int chunk = (N + 1023) >> 10;
    const int start = t * chunk;
    const int end = min(start + chunk, N);

    int s = 0;
    for (int i = start; i < end; i++) s += deg[i];
    part[t] = s;
    __syncthreads();
    for (int o = 1; o < 1024; o <<= 1) {
        int v = (t >= o) ? part[t - o] : 0;
        __syncthreads();
        part[t] += v;
        __syncthreads();
    }
    int base = (t == 0) ? 0 : part[t - 1];
    for (int i = start; i < end; i++) {
        off[i] = base;
        cur[i] = base;
        base += deg[i];
    }
    if (t == 1023) off[N] = part[1023];
}

__global__ __launch_bounds__(256) void fill_kernel(
    const int* __restrict__ src, const int* __restrict__ dst,
    int* __restrict__ cur, int* __restrict__ csrc, int E)
{
    int e = (blockIdx.x * blockDim.x + threadIdx.x) * 8;
    if (e + 7 < E) {
        int4 s0 = *(const int4*)(src + e);
        int4 d0 = *(const int4*)(dst + e);
        int4 s1 = *(const int4*)(src + e + 4);
        int4 d1 = *(const int4*)(dst + e + 4);
        csrc[atomicAdd(&cur[d0.x], 1)] = s0.x;
        csrc[atomicAdd(&cur[d0.y], 1)] = s0.y;
        csrc[atomicAdd(&cur[d0.z], 1)] = s0.z;
        csrc[atomicAdd(&cur[d0.w], 1)] = s0.w;
        csrc[atomicAdd(&cur[d1.x], 1)] = s1.x;
        csrc[atomicAdd(&cur[d1.y], 1)] = s1.y;
        csrc[atomicAdd(&cur[d1.z], 1)] = s1.z;
        csrc[atomicAdd(&cur[d1.w], 1)] = s1.w;
    } else {
        for (int j = e; j < E; j++)
            csrc[atomicAdd(&cur[dst[j]], 1)] = src[j];
    }
}

// ---------------------------------------------------------------------------
// Gather-aggregate (pairnorm rownorm fused; colsum for next layer's colmean)
// ---------------------------------------------------------------------------
template <int N4, bool PAIRNORM>
__global__ __launch_bounds__(256) void gather_kernel(
    const float4* __restrict__ tmp, const int* __restrict__ off,
    const int* __restrict__ csrc, const float* __restrict__ norm,
    const float* __restrict__ bias, float4* __restrict__ xout,
    float* __restrict__ colsum, int M)
{
    constexpr int RPB = 256 / N4;
    const int lane = threadIdx.x % N4;
    const int rl = threadIdx.x / N4;

    float4 bb = ((const float4*)bias)[lane];
    float4 lsum = make_float4(0.f, 0.f, 0.f, 0.f);

    for (int r = blockIdx.x * RPB + rl; r < M; r += gridDim.x * RPB) {
        int s0 = __ldg(off + r);
        int s1 = __ldg(off + r + 1);
        float4 acc = make_float4(0.f, 0.f, 0.f, 0.f);
        int i = s0;
        for (; i + 3 < s1; i += 4) {
            int sa = __ldg(csrc + i);
            int sb = __ldg(csrc + i + 1);
            int sc = __ldg(csrc + i + 2);
            int sd = __ldg(csrc + i + 3);
            float4 va = tmp[(size_t)sa * N4 + lane];
            float4 vb = tmp[(size_t)sb * N4 + lane];
            float4 vc = tmp[(size_t)sc * N4 + lane];
            float4 vd = tmp[(size_t)sd * N4 + lane];
            acc.x += (va.x + vb.x) + (vc.x + vd.x);
            acc.y += (va.y + vb.y) + (vc.y + vd.y);
            acc.z += (va.z + vb.z) + (vc.z + vd.z);
            acc.w += (va.w + vb.w) + (vc.w + vd.w);
        }
        for (; i < s1; i++) {
            int sa = __ldg(csrc + i);
            float4 va = tmp[(size_t)sa * N4 + lane];
            acc.x += va.x; acc.y += va.y; acc.z += va.z; acc.w += va.w;
        }
        float nm = norm[r];
        float4 v;
        v.x = acc.x * nm + bb.x;
        v.y = acc.y * nm + bb.y;
        v.z = acc.z * nm + bb.z;
        v.w = acc.w * nm + bb.w;
        if (PAIRNORM) {
            lsum.x += v.x; lsum.y += v.y; lsum.z += v.z; lsum.w += v.w;
            float ss = v.x * v.x + v.y * v.y + v.z * v.z + v.w * v.w;
#pragma unroll
            for (int o = 16; o > 0; o >>= 1)
                ss += __shfl_xor_sync(0xffffffffu, ss, o);
            float rinv = rsqrtf(1e-6f + ss);
            v.x *= rinv; v.y *= rinv; v.z *= rinv; v.w *= rinv;
        }
        xout[(size_t)r * N4 + lane] = v;
    }

    if (PAIRNORM) {
        __shared__ float scol[N4 * 4];
        if (threadIdx.x < N4 * 4) scol[threadIdx.x] = 0.0f;
        __syncthreads();
        atomicAdd(&scol[lane * 4 + 0], lsum.x);
        atomicAdd(&scol[lane * 4 + 1], lsum.y);
        atomicAdd(&scol[lane * 4 + 2], lsum.z);
        atomicAdd(&scol[lane * 4 + 3], lsum.w);
        __syncthreads();
        if (threadIdx.x < N4 * 4)
            atomicAdd(&colsum[threadIdx.x], scol[threadIdx.x]);
    }
}

// ---------------------------------------------------------------------------
// Launch: CSR build forked onto a side stream, overlapped with wconv+gemm1.
// ---------------------------------------------------------------------------
extern "C" void kernel_launch(void* const* d_in, const int* in_sizes, int n_in,
                              void* d_out, int out_size)
{
    const float* in_feat = (const float*)d_in[0];
    const int*   src     = (const int*)  d_in[1];
    const int*   dst     = (const int*)  d_in[2];
    const float* norm    = (const float*)d_in[3];
    const float* W1      = (const float*)d_in[4];
    const float* b1      = (const float*)d_in[5];
    const float* W2      = (const float*)d_in[6];
    const float* b2      = (const float*)d_in[7];
    const float* W3      = (const float*)d_in[8];
    const float* b3      = (const float*)d_in[9];
    float* out = (float*)d_out;

    const int M = in_sizes[3];
    const int E = in_sizes[1];
    const float invM = 1.0f / (float)M;

    float *tmp, *y, *colsumA, *colsumB;
    int *deg, *off, *cur, *csrc;
    __nv_bfloat16 *w1h, *w1l, *w2h, *w2l, *w3h, *w3l;
    cudaGetSymbolAddress((void**)&tmp,     g_tmp);
    cudaGetSymbolAddress((void**)&y,       g_y);
    cudaGetSymbolAddress((void**)&colsumA, g_colsumA);
    cudaGetSymbolAddress((void**)&colsumB, g_colsumB);
    cudaGetSymbolAddress((void**)&deg,     g_deg);
    cudaGetSymbolAddress((void**)&off,     g_off);
    cudaGetSymbolAddress((void**)&cur,     g_cur);
    cudaGetSymbolAddress((void**)&csrc,    g_csrc);
    cudaGetSymbolAddress((void**)&w1h,     g_w1h);
    cudaGetSymbolAddress((void**)&w1l,     g_w1l);
    cudaGetSymbolAddress((void**)&w2h,     g_w2h);
    cudaGetSymbolAddress((void**)&w2l,     g_w2l);
    cudaGetSymbolAddress((void**)&w3h,     g_w3h);
    cudaGetSymbolAddress((void**)&w3l,     g_w3l);

    constexpr int SMEM_128 = 2 * (2 * 128 * 20 + 2 * 128 * 20) * 4;  // 81920
    constexpr int SMEM_64  = 2 * (2 * 128 * 20 + 2 * 64  * 20) * 4;  // 61440

    // One-time resource init (host-side objects only; created on the
    // uncaptured correctness call, reused identically on every call).
    static cudaStream_t side = nullptr;
    static cudaEvent_t evFork = nullptr, evJoin = nullptr;
    if (!side) {
        cudaStreamCreateWithFlags(&side, cudaStreamNonBlocking);
        cudaEventCreateWithFlags(&evFork, cudaEventDisableTiming);
        cudaEventCreateWithFlags(&evJoin, cudaEventDisableTiming);
        cudaFuncSetAttribute(gemm_tc_kernel<256, 128, false>,
                             cudaFuncAttributeMaxDynamicSharedMemorySize, SMEM_128);
        cudaFuncSetAttribute(gemm_tc_kernel<128, 128, true>,
                             cudaFuncAttributeMaxDynamicSharedMemorySize, SMEM_128);
        cudaFuncSetAttribute(gemm_tc_kernel<128, 64, true>,
                             cudaFuncAttributeMaxDynamicSharedMemorySize, SMEM_64);
    }

    const int gemm_blocks = (M + 127) / 128;
    const int GATHER_BLOCKS = (M + 7) / 8;
    const int GATHER_BLOCKS3 = (M + 15) / 16;
    const int E8_BLOCKS = ((E + 7) / 8 + 255) / 256;

    // ---- fork: CSR build on side stream ----
    cudaEventRecord(evFork, 0);
    cudaStreamWaitEvent(side, evFork, 0);
    cudaMemsetAsync(deg, 0, (size_t)M * sizeof(int), side);
    hist_kernel<<<E8_BLOCKS, 256, 0, side>>>(dst, deg, E);
    scan_kernel<<<1, 1024, 0, side>>>(deg, off, cur, M);
    fill_kernel<<<E8_BLOCKS, 256, 0, side>>>(src, dst, cur, csrc, E);
    cudaEventRecord(evJoin, side);

    // ---- main: weight conversion + layer-1 GEMM (independent of CSR) ----
    wconv3_kernel<<<224, 256>>>(W1, W2, W3, w1h, w1l, w2h, w2l, w3h, w3l);
    gemm_tc_kernel<256, 128, false><<<gemm_blocks, 256, SMEM_128>>>(
        in_feat, nullptr, 0.0f, w1h, w1l, norm, tmp, M, colsumA);

    // ---- join: gather1 needs CSR + tmp ----
    cudaStreamWaitEvent(0, evJoin, 0);
    gather_kernel<32, true><<<GATHER_BLOCKS, 256>>>(
        (const float4*)tmp, off, csrc, norm, b1, (float4*)y, colsumA, M);

    // ---------------- Layer 2: 128 -> 128 ----------------
    gemm_tc_kernel<128, 128, true><<<gemm_blocks, 256, SMEM_128>>>(
        y, colsumA, invM, w2h, w2l, norm, tmp, M, colsumB);
    gather_kernel<32, true><<<GATHER_BLOCKS, 256>>>(
        (const float4*)tmp, off, csrc, norm, b2, (float4*)y, colsumB, M);

    // ---------------- Layer 3: 128 -> 64 ----------------
    gemm_tc_kernel<128, 64, true><<<gemm_blocks, 256, SMEM_64>>>(
        y, colsumB, invM, w3h, w3l, norm, tmp, M, nullptr);
    gather_kernel<16, false><<<GATHER_BLOCKS3, 256>>>(
        (const float4*)tmp, off, csrc, norm, b3, (float4*)out, nullptr, M);
}